// round 1
// baseline (speedup 1.0000x reference)
#include <cuda_runtime.h>

#define BATCH 8
#define SEQ   2048
#define EMB   1024
#define HD    64
#define NROWS (BATCH*SEQ)   // 16384

typedef unsigned long long u64;

// ---- scratch (device globals: allocation-free rule) ----
__device__ float g_q[NROWS*HD];
__device__ float g_k[NROWS*HD];
__device__ float g_v[NROWS*HD];                 // becomes v/D in-place (rewritten every launch)
__device__ float g_s[(size_t)BATCH*SEQ*SEQ];    // 128 MB scores / exp(scores)
__device__ float g_Dp[4][BATCH*SEQ];            // split column sums (deterministic reduce)

// ---- packed fp32x2 helpers (FFMA2) ----
__device__ __forceinline__ u64 pk2(float x, float y) {
    u64 r;
    asm("mov.b64 %0, {%1, %2};" : "=l"(r) : "r"(__float_as_uint(x)), "r"(__float_as_uint(y)));
    return r;
}
__device__ __forceinline__ void fma2(u64& d, u64 a, u64 b) {
    asm("fma.rn.f32x2 %0, %1, %2, %0;" : "+l"(d) : "l"(a), "l"(b));
}
__device__ __forceinline__ float2 up2(u64 v) {
    unsigned int x, y;
    asm("mov.b64 {%0, %1}, %2;" : "=r"(x), "=r"(y) : "l"(v));
    return make_float2(__uint_as_float(x), __uint_as_float(y));
}

// =====================================================================
// K1: fused QKV GEMM.  C[M,64] = X[M,1024] @ W[64,1024]^T
// BM=128, BN=64, BK=16, 128 threads, 8x8 per thread via f32x2.
// grid = (M/128, 3)  (y selects Wq/Wk/Wv)
// =====================================================================
__global__ void __launch_bounds__(128) qkv_kernel(
    const float* __restrict__ X,
    const float* __restrict__ Wq,
    const float* __restrict__ Wk,
    const float* __restrict__ Wv)
{
    __shared__ float As[16][132];
    __shared__ float Bs[16][68];

    const int tid = threadIdx.x;
    const int tx  = tid & 7;
    const int ty  = tid >> 3;
    const int m0  = blockIdx.x * 128;

    const float* W;
    float* Out;
    if      (blockIdx.y == 0) { W = Wq; Out = g_q; }
    else if (blockIdx.y == 1) { W = Wk; Out = g_k; }
    else                      { W = Wv; Out = g_v; }

    const int lr = tid >> 2;        // 0..31
    const int lc = (tid & 3) * 4;   // 0,4,8,12

    u64 acc[8][4];
    #pragma unroll
    for (int m = 0; m < 8; m++)
        #pragma unroll
        for (int n = 0; n < 4; n++) acc[m][n] = 0ULL;

    float4 pa[4], pb[2];
    #pragma unroll
    for (int p = 0; p < 4; p++)
        pa[p] = *(const float4*)&X[(size_t)(m0 + lr + 32*p) * EMB + lc];
    #pragma unroll
    for (int p = 0; p < 2; p++)
        pb[p] = *(const float4*)&W[(size_t)(lr + 32*p) * EMB + lc];

    for (int kt = 0; kt < EMB/16; kt++) {
        #pragma unroll
        for (int p = 0; p < 4; p++) {
            As[lc+0][lr+32*p] = pa[p].x;
            As[lc+1][lr+32*p] = pa[p].y;
            As[lc+2][lr+32*p] = pa[p].z;
            As[lc+3][lr+32*p] = pa[p].w;
        }
        #pragma unroll
        for (int p = 0; p < 2; p++) {
            Bs[lc+0][lr+32*p] = pb[p].x;
            Bs[lc+1][lr+32*p] = pb[p].y;
            Bs[lc+2][lr+32*p] = pb[p].z;
            Bs[lc+3][lr+32*p] = pb[p].w;
        }
        __syncthreads();
        if (kt + 1 < EMB/16) {
            const int c = (kt+1)*16 + lc;
            #pragma unroll
            for (int p = 0; p < 4; p++)
                pa[p] = *(const float4*)&X[(size_t)(m0 + lr + 32*p) * EMB + c];
            #pragma unroll
            for (int p = 0; p < 2; p++)
                pb[p] = *(const float4*)&W[(size_t)(lr + 32*p) * EMB + c];
        }
        #pragma unroll
        for (int kk = 0; kk < 16; kk++) {
            float4 a0 = *(const float4*)&As[kk][ty*8];
            float4 a1 = *(const float4*)&As[kk][ty*8+4];
            u64 b0 = *(const u64*)&Bs[kk][tx*8+0];
            u64 b1 = *(const u64*)&Bs[kk][tx*8+2];
            u64 b2 = *(const u64*)&Bs[kk][tx*8+4];
            u64 b3 = *(const u64*)&Bs[kk][tx*8+6];
            float am[8] = {a0.x,a0.y,a0.z,a0.w,a1.x,a1.y,a1.z,a1.w};
            #pragma unroll
            for (int m = 0; m < 8; m++) {
                u64 aa = pk2(am[m], am[m]);
                fma2(acc[m][0], aa, b0);
                fma2(acc[m][1], aa, b1);
                fma2(acc[m][2], aa, b2);
                fma2(acc[m][3], aa, b3);
            }
        }
        __syncthreads();
    }

    #pragma unroll
    for (int m = 0; m < 8; m++) {
        const size_t row = (size_t)m0 + ty*8 + m;
        float2 c0 = up2(acc[m][0]);
        float2 c1 = up2(acc[m][1]);
        float2 c2 = up2(acc[m][2]);
        float2 c3 = up2(acc[m][3]);
        *(float4*)&Out[row*HD + tx*8]     = make_float4(c0.x, c0.y, c1.x, c1.y);
        *(float4*)&Out[row*HD + tx*8 + 4] = make_float4(c2.x, c2.y, c3.x, c3.y);
    }
}

// =====================================================================
// K2: scores.  S[b] = Q[b] (2048x64) @ K[b]^T  -> g_s [b][i][k]
// BM=BN=128, BK=16, 256 threads, 8x8 per thread via f32x2.
// grid = (16, 16, 8)
// =====================================================================
__global__ void __launch_bounds__(256) scores_kernel()
{
    __shared__ float Qs[16][132];
    __shared__ float Ks[16][132];

    const int tid = threadIdx.x;
    const int tx  = tid & 15;
    const int ty  = tid >> 4;
    const int b   = blockIdx.z;
    const int i0  = blockIdx.y * 128;
    const int j0  = blockIdx.x * 128;

    const float* Q = g_q + (size_t)b * SEQ * HD;
    const float* K = g_k + (size_t)b * SEQ * HD;

    const int lr = tid >> 2;        // 0..63
    const int lc = (tid & 3) * 4;

    u64 acc[8][4];
    #pragma unroll
    for (int m = 0; m < 8; m++)
        #pragma unroll
        for (int n = 0; n < 4; n++) acc[m][n] = 0ULL;

    float4 pq[2], pk[2];
    #pragma unroll
    for (int p = 0; p < 2; p++) {
        pq[p] = *(const float4*)&Q[(size_t)(i0 + lr + 64*p) * HD + lc];
        pk[p] = *(const float4*)&K[(size_t)(j0 + lr + 64*p) * HD + lc];
    }

    for (int kt = 0; kt < HD/16; kt++) {
        #pragma unroll
        for (int p = 0; p < 2; p++) {
            Qs[lc+0][lr+64*p] = pq[p].x;
            Qs[lc+1][lr+64*p] = pq[p].y;
            Qs[lc+2][lr+64*p] = pq[p].z;
            Qs[lc+3][lr+64*p] = pq[p].w;
            Ks[lc+0][lr+64*p] = pk[p].x;
            Ks[lc+1][lr+64*p] = pk[p].y;
            Ks[lc+2][lr+64*p] = pk[p].z;
            Ks[lc+3][lr+64*p] = pk[p].w;
        }
        __syncthreads();
        if (kt + 1 < HD/16) {
            const int c = (kt+1)*16 + lc;
            #pragma unroll
            for (int p = 0; p < 2; p++) {
                pq[p] = *(const float4*)&Q[(size_t)(i0 + lr + 64*p) * HD + c];
                pk[p] = *(const float4*)&K[(size_t)(j0 + lr + 64*p) * HD + c];
            }
        }
        #pragma unroll
        for (int kk = 0; kk < 16; kk++) {
            float4 a0 = *(const float4*)&Qs[kk][ty*8];
            float4 a1 = *(const float4*)&Qs[kk][ty*8+4];
            u64 b0 = *(const u64*)&Ks[kk][tx*8+0];
            u64 b1 = *(const u64*)&Ks[kk][tx*8+2];
            u64 b2 = *(const u64*)&Ks[kk][tx*8+4];
            u64 b3 = *(const u64*)&Ks[kk][tx*8+6];
            float am[8] = {a0.x,a0.y,a0.z,a0.w,a1.x,a1.y,a1.z,a1.w};
            #pragma unroll
            for (int m = 0; m < 8; m++) {
                u64 aa = pk2(am[m], am[m]);
                fma2(acc[m][0], aa, b0);
                fma2(acc[m][1], aa, b1);
                fma2(acc[m][2], aa, b2);
                fma2(acc[m][3], aa, b3);
            }
        }
        __syncthreads();
    }

    float* S = g_s + (size_t)b * SEQ * SEQ;
    #pragma unroll
    for (int m = 0; m < 8; m++) {
        const size_t row = (size_t)(i0 + ty*8 + m);
        float2 c0 = up2(acc[m][0]);
        float2 c1 = up2(acc[m][1]);
        float2 c2 = up2(acc[m][2]);
        float2 c3 = up2(acc[m][3]);
        *(float4*)&S[row*SEQ + j0 + tx*8]     = make_float4(c0.x, c0.y, c1.x, c1.y);
        *(float4*)&S[row*SEQ + j0 + tx*8 + 4] = make_float4(c2.x, c2.y, c3.x, c3.y);
    }
}

// =====================================================================
// K3: e = exp(s) in place + partial column sums (over query axis i).
// No max subtraction needed: |s| <= ~47, exp fits fp32; e/D <= 1 later.
// grid = (8 colchunks, 8 batch, 4 rowchunks), 256 threads.
// =====================================================================
__global__ void __launch_bounds__(256) expsum_kernel()
{
    const int k  = blockIdx.x * 256 + threadIdx.x;
    const int b  = blockIdx.y;
    const int iz = blockIdx.z;
    float* S = g_s + (size_t)b * SEQ * SEQ + k;
    const int i0 = iz * (SEQ/4);
    float sum = 0.0f;
    #pragma unroll 8
    for (int i = i0; i < i0 + SEQ/4; i++) {
        float e = __expf(S[(size_t)i * SEQ]);
        S[(size_t)i * SEQ] = e;
        sum += e;
    }
    g_Dp[iz][b * SEQ + k] = sum;
}

// =====================================================================
// K4: v' = v / D  (fold softmax denominator into V; deterministic reduce)
// =====================================================================
__global__ void __launch_bounds__(256) vscale_kernel()
{
    const int idx = blockIdx.x * 256 + threadIdx.x;   // < NROWS*HD
    const int bk  = idx >> 6;
    const float D = g_Dp[0][bk] + g_Dp[1][bk] + g_Dp[2][bk] + g_Dp[3][bk];
    g_v[idx] = g_v[idx] * (1.0f / D);
}

// =====================================================================
// K5: O[b] = E[b] (2048x2048) @ V'[b] (2048x64), written 16x tiled.
// BM=128, BN=64, BK=16, 128 threads, 8x8 per thread via f32x2.
// grid = (16, 1, 8)
// =====================================================================
__global__ void __launch_bounds__(128) pv_kernel(float* __restrict__ Out)
{
    __shared__ float Es[16][132];
    __shared__ float Vs[16][68];

    const int tid = threadIdx.x;
    const int tx  = tid & 7;
    const int ty  = tid >> 3;
    const int b   = blockIdx.z;
    const int i0  = blockIdx.x * 128;

    const float* E = g_s + (size_t)b * SEQ * SEQ;
    const float* V = g_v + (size_t)b * SEQ * HD;

    const int lr = tid >> 2;        // 0..31 (E loads)
    const int lc = (tid & 3) * 4;
    const int vr = tid >> 4;        // 0..7  (V loads)
    const int vc = (tid & 15) * 4;

    u64 acc[8][4];
    #pragma unroll
    for (int m = 0; m < 8; m++)
        #pragma unroll
        for (int n = 0; n < 4; n++) acc[m][n] = 0ULL;

    float4 pe[4], pv[2];
    #pragma unroll
    for (int p = 0; p < 4; p++)
        pe[p] = *(const float4*)&E[(size_t)(i0 + lr + 32*p) * SEQ + lc];
    #pragma unroll
    for (int p = 0; p < 2; p++)
        pv[p] = *(const float4*)&V[(size_t)(vr + 8*p) * HD + vc];

    for (int kt = 0; kt < SEQ/16; kt++) {
        #pragma unroll
        for (int p = 0; p < 4; p++) {
            Es[lc+0][lr+32*p] = pe[p].x;
            Es[lc+1][lr+32*p] = pe[p].y;
            Es[lc+2][lr+32*p] = pe[p].z;
            Es[lc+3][lr+32*p] = pe[p].w;
        }
        #pragma unroll
        for (int p = 0; p < 2; p++)
            *(float4*)&Vs[vr+8*p][vc] = pv[p];
        __syncthreads();
        if (kt + 1 < SEQ/16) {
            const int c = (kt+1)*16;
            #pragma unroll
            for (int p = 0; p < 4; p++)
                pe[p] = *(const float4*)&E[(size_t)(i0 + lr + 32*p) * SEQ + c + lc];
            #pragma unroll
            for (int p = 0; p < 2; p++)
                pv[p] = *(const float4*)&V[(size_t)(c + vr + 8*p) * HD + vc];
        }
        #pragma unroll
        for (int kk = 0; kk < 16; kk++) {
            float4 a0 = *(const float4*)&Es[kk][ty*8];
            float4 a1 = *(const float4*)&Es[kk][ty*8+4];
            u64 b0 = *(const u64*)&Vs[kk][tx*8+0];
            u64 b1 = *(const u64*)&Vs[kk][tx*8+2];
            u64 b2 = *(const u64*)&Vs[kk][tx*8+4];
            u64 b3 = *(const u64*)&Vs[kk][tx*8+6];
            float am[8] = {a0.x,a0.y,a0.z,a0.w,a1.x,a1.y,a1.z,a1.w};
            #pragma unroll
            for (int m = 0; m < 8; m++) {
                u64 aa = pk2(am[m], am[m]);
                fma2(acc[m][0], aa, b0);
                fma2(acc[m][1], aa, b1);
                fma2(acc[m][2], aa, b2);
                fma2(acc[m][3], aa, b3);
            }
        }
        __syncthreads();
    }

    // write out, tiled 16x across heads (all heads identical)
    #pragma unroll
    for (int m = 0; m < 8; m++) {
        const size_t row = (size_t)b * SEQ + i0 + ty*8 + m;
        float2 c0 = up2(acc[m][0]);
        float2 c1 = up2(acc[m][1]);
        float2 c2 = up2(acc[m][2]);
        float2 c3 = up2(acc[m][3]);
        float4 o0 = make_float4(c0.x, c0.y, c1.x, c1.y);
        float4 o1 = make_float4(c2.x, c2.y, c3.x, c3.y);
        const size_t base = row * (size_t)(HD*16) + tx*8;
        #pragma unroll
        for (int h = 0; h < 16; h++) {
            *(float4*)&Out[base + h*HD]     = o0;
            *(float4*)&Out[base + h*HD + 4] = o1;
        }
    }
}

extern "C" void kernel_launch(void* const* d_in, const int* in_sizes, int n_in,
                              void* d_out, int out_size)
{
    const float* x  = (const float*)d_in[0];
    const float* Wq = (const float*)d_in[1];
    const float* Wk = (const float*)d_in[2];
    const float* Wv = (const float*)d_in[3];
    float* out = (float*)d_out;

    qkv_kernel<<<dim3(NROWS/128, 3), 128>>>(x, Wq, Wk, Wv);
    scores_kernel<<<dim3(SEQ/128, SEQ/128, BATCH), 256>>>();
    expsum_kernel<<<dim3(SEQ/256, BATCH, 4), 256>>>();
    vscale_kernel<<<dim3((NROWS*HD)/256), 256>>>();
    pv_kernel<<<dim3(SEQ/128, 1, BATCH), 128>>>(out);
}

// round 2
// speedup vs baseline: 1.0009x; 1.0009x over previous
#include <cuda_runtime.h>

#define BATCH 8
#define SEQ   2048
#define EMB   1024
#define HD    64
#define NROWS (BATCH*SEQ)   // 16384

typedef unsigned long long u64;

// ---- scratch (device globals: allocation-free rule) ----
__device__ float g_q[NROWS*HD];
__device__ float g_k[NROWS*HD];
__device__ float g_v[NROWS*HD];                 // becomes v/D in-place (rewritten every launch)
__device__ float g_s[(size_t)BATCH*SEQ*SEQ];    // 128 MB scores / exp(scores)
__device__ float g_Dp[4][BATCH*SEQ];            // split column sums (deterministic reduce)

// ---- packed fp32x2 helpers (FFMA2) ----
__device__ __forceinline__ u64 pk2(float x, float y) {
    u64 r;
    asm("mov.b64 %0, {%1, %2};" : "=l"(r) : "r"(__float_as_uint(x)), "r"(__float_as_uint(y)));
    return r;
}
__device__ __forceinline__ void fma2(u64& d, u64 a, u64 b) {
    asm("fma.rn.f32x2 %0, %1, %2, %0;" : "+l"(d) : "l"(a), "l"(b));
}
__device__ __forceinline__ float2 up2(u64 v) {
    unsigned int x, y;
    asm("mov.b64 {%0, %1}, %2;" : "=r"(x), "=r"(y) : "l"(v));
    return make_float2(__uint_as_float(x), __uint_as_float(y));
}

// =====================================================================
// K1: fused QKV GEMM.  C[M,64] = X[M,1024] @ W[64,1024]^T
// BM=128, BN=64, BK=16, 128 threads, 8x8 per thread via f32x2.
// grid = (M/128, 3)  (y selects Wq/Wk/Wv)
// =====================================================================
__global__ void __launch_bounds__(128) qkv_kernel(
    const float* __restrict__ X,
    const float* __restrict__ Wq,
    const float* __restrict__ Wk,
    const float* __restrict__ Wv)
{
    __shared__ float As[16][132];
    __shared__ float Bs[16][68];

    const int tid = threadIdx.x;
    const int tx  = tid & 7;
    const int ty  = tid >> 3;
    const int m0  = blockIdx.x * 128;

    const float* W;
    float* Out;
    if      (blockIdx.y == 0) { W = Wq; Out = g_q; }
    else if (blockIdx.y == 1) { W = Wk; Out = g_k; }
    else                      { W = Wv; Out = g_v; }

    const int lr = tid >> 2;        // 0..31
    const int lc = (tid & 3) * 4;   // 0,4,8,12

    u64 acc[8][4];
    #pragma unroll
    for (int m = 0; m < 8; m++)
        #pragma unroll
        for (int n = 0; n < 4; n++) acc[m][n] = 0ULL;

    float4 pa[4], pb[2];
    #pragma unroll
    for (int p = 0; p < 4; p++)
        pa[p] = *(const float4*)&X[(size_t)(m0 + lr + 32*p) * EMB + lc];
    #pragma unroll
    for (int p = 0; p < 2; p++)
        pb[p] = *(const float4*)&W[(size_t)(lr + 32*p) * EMB + lc];

    for (int kt = 0; kt < EMB/16; kt++) {
        #pragma unroll
        for (int p = 0; p < 4; p++) {
            As[lc+0][lr+32*p] = pa[p].x;
            As[lc+1][lr+32*p] = pa[p].y;
            As[lc+2][lr+32*p] = pa[p].z;
            As[lc+3][lr+32*p] = pa[p].w;
        }
        #pragma unroll
        for (int p = 0; p < 2; p++) {
            Bs[lc+0][lr+32*p] = pb[p].x;
            Bs[lc+1][lr+32*p] = pb[p].y;
            Bs[lc+2][lr+32*p] = pb[p].z;
            Bs[lc+3][lr+32*p] = pb[p].w;
        }
        __syncthreads();
        if (kt + 1 < EMB/16) {
            const int c = (kt+1)*16 + lc;
            #pragma unroll
            for (int p = 0; p < 4; p++)
                pa[p] = *(const float4*)&X[(size_t)(m0 + lr + 32*p) * EMB + c];
            #pragma unroll
            for (int p = 0; p < 2; p++)
                pb[p] = *(const float4*)&W[(size_t)(lr + 32*p) * EMB + c];
        }
        #pragma unroll
        for (int kk = 0; kk < 16; kk++) {
            float4 a0 = *(const float4*)&As[kk][ty*8];
            float4 a1 = *(const float4*)&As[kk][ty*8+4];
            u64 b0 = *(const u64*)&Bs[kk][tx*8+0];
            u64 b1 = *(const u64*)&Bs[kk][tx*8+2];
            u64 b2 = *(const u64*)&Bs[kk][tx*8+4];
            u64 b3 = *(const u64*)&Bs[kk][tx*8+6];
            float am[8] = {a0.x,a0.y,a0.z,a0.w,a1.x,a1.y,a1.z,a1.w};
            #pragma unroll
            for (int m = 0; m < 8; m++) {
                u64 aa = pk2(am[m], am[m]);
                fma2(acc[m][0], aa, b0);
                fma2(acc[m][1], aa, b1);
                fma2(acc[m][2], aa, b2);
                fma2(acc[m][3], aa, b3);
            }
        }
        __syncthreads();
    }

    #pragma unroll
    for (int m = 0; m < 8; m++) {
        const size_t row = (size_t)m0 + ty*8 + m;
        float2 c0 = up2(acc[m][0]);
        float2 c1 = up2(acc[m][1]);
        float2 c2 = up2(acc[m][2]);
        float2 c3 = up2(acc[m][3]);
        *(float4*)&Out[row*HD + tx*8]     = make_float4(c0.x, c0.y, c1.x, c1.y);
        *(float4*)&Out[row*HD + tx*8 + 4] = make_float4(c2.x, c2.y, c3.x, c3.y);
    }
}

// =====================================================================
// K2: scores.  S[b] = Q[b] (2048x64) @ K[b]^T  -> g_s [b][i][k]
// BM=BN=128, BK=16, 256 threads, 8x8 per thread via f32x2.
// grid = (16, 16, 8)
// =====================================================================
__global__ void __launch_bounds__(256) scores_kernel()
{
    __shared__ float Qs[16][132];
    __shared__ float Ks[16][132];

    const int tid = threadIdx.x;
    const int tx  = tid & 15;
    const int ty  = tid >> 4;
    const int b   = blockIdx.z;
    const int i0  = blockIdx.y * 128;
    const int j0  = blockIdx.x * 128;

    const float* Q = g_q + (size_t)b * SEQ * HD;
    const float* K = g_k + (size_t)b * SEQ * HD;

    const int lr = tid >> 2;        // 0..63
    const int lc = (tid & 3) * 4;

    u64 acc[8][4];
    #pragma unroll
    for (int m = 0; m < 8; m++)
        #pragma unroll
        for (int n = 0; n < 4; n++) acc[m][n] = 0ULL;

    float4 pq[2], pk[2];
    #pragma unroll
    for (int p = 0; p < 2; p++) {
        pq[p] = *(const float4*)&Q[(size_t)(i0 + lr + 64*p) * HD + lc];
        pk[p] = *(const float4*)&K[(size_t)(j0 + lr + 64*p) * HD + lc];
    }

    for (int kt = 0; kt < HD/16; kt++) {
        #pragma unroll
        for (int p = 0; p < 2; p++) {
            Qs[lc+0][lr+64*p] = pq[p].x;
            Qs[lc+1][lr+64*p] = pq[p].y;
            Qs[lc+2][lr+64*p] = pq[p].z;
            Qs[lc+3][lr+64*p] = pq[p].w;
            Ks[lc+0][lr+64*p] = pk[p].x;
            Ks[lc+1][lr+64*p] = pk[p].y;
            Ks[lc+2][lr+64*p] = pk[p].z;
            Ks[lc+3][lr+64*p] = pk[p].w;
        }
        __syncthreads();
        if (kt + 1 < HD/16) {
            const int c = (kt+1)*16 + lc;
            #pragma unroll
            for (int p = 0; p < 2; p++) {
                pq[p] = *(const float4*)&Q[(size_t)(i0 + lr + 64*p) * HD + c];
                pk[p] = *(const float4*)&K[(size_t)(j0 + lr + 64*p) * HD + c];
            }
        }
        #pragma unroll
        for (int kk = 0; kk < 16; kk++) {
            float4 a0 = *(const float4*)&Qs[kk][ty*8];
            float4 a1 = *(const float4*)&Qs[kk][ty*8+4];
            u64 b0 = *(const u64*)&Ks[kk][tx*8+0];
            u64 b1 = *(const u64*)&Ks[kk][tx*8+2];
            u64 b2 = *(const u64*)&Ks[kk][tx*8+4];
            u64 b3 = *(const u64*)&Ks[kk][tx*8+6];
            float am[8] = {a0.x,a0.y,a0.z,a0.w,a1.x,a1.y,a1.z,a1.w};
            #pragma unroll
            for (int m = 0; m < 8; m++) {
                u64 aa = pk2(am[m], am[m]);
                fma2(acc[m][0], aa, b0);
                fma2(acc[m][1], aa, b1);
                fma2(acc[m][2], aa, b2);
                fma2(acc[m][3], aa, b3);
            }
        }
        __syncthreads();
    }

    float* S = g_s + (size_t)b * SEQ * SEQ;
    #pragma unroll
    for (int m = 0; m < 8; m++) {
        const size_t row = (size_t)(i0 + ty*8 + m);
        float2 c0 = up2(acc[m][0]);
        float2 c1 = up2(acc[m][1]);
        float2 c2 = up2(acc[m][2]);
        float2 c3 = up2(acc[m][3]);
        *(float4*)&S[row*SEQ + j0 + tx*8]     = make_float4(c0.x, c0.y, c1.x, c1.y);
        *(float4*)&S[row*SEQ + j0 + tx*8 + 4] = make_float4(c2.x, c2.y, c3.x, c3.y);
    }
}

// =====================================================================
// K3: e = exp(s) in place + partial column sums (over query axis i).
// No max subtraction needed: |s| <= ~47, exp fits fp32; e/D <= 1 later.
// grid = (8 colchunks, 8 batch, 4 rowchunks), 256 threads.
// =====================================================================
__global__ void __launch_bounds__(256) expsum_kernel()
{
    const int k  = blockIdx.x * 256 + threadIdx.x;
    const int b  = blockIdx.y;
    const int iz = blockIdx.z;
    float* S = g_s + (size_t)b * SEQ * SEQ + k;
    const int i0 = iz * (SEQ/4);
    float sum = 0.0f;
    #pragma unroll 8
    for (int i = i0; i < i0 + SEQ/4; i++) {
        float e = __expf(S[(size_t)i * SEQ]);
        S[(size_t)i * SEQ] = e;
        sum += e;
    }
    g_Dp[iz][b * SEQ + k] = sum;
}

// =====================================================================
// K4: v' = v / D  (fold softmax denominator into V; deterministic reduce)
// =====================================================================
__global__ void __launch_bounds__(256) vscale_kernel()
{
    const int idx = blockIdx.x * 256 + threadIdx.x;   // < NROWS*HD
    const int bk  = idx >> 6;
    const float D = g_Dp[0][bk] + g_Dp[1][bk] + g_Dp[2][bk] + g_Dp[3][bk];
    g_v[idx] = g_v[idx] * (1.0f / D);
}

// =====================================================================
// K5: O[b] = E[b] (2048x2048) @ V'[b] (2048x64), written 16x tiled.
// BM=128, BN=64, BK=16, 128 threads, 8x8 per thread via f32x2.
// grid = (16, 1, 8)
// =====================================================================
__global__ void __launch_bounds__(128) pv_kernel(float* __restrict__ Out)
{
    __shared__ float Es[16][132];
    __shared__ float Vs[16][68];

    const int tid = threadIdx.x;
    const int tx  = tid & 7;
    const int ty  = tid >> 3;
    const int b   = blockIdx.z;
    const int i0  = blockIdx.x * 128;

    const float* E = g_s + (size_t)b * SEQ * SEQ;
    const float* V = g_v + (size_t)b * SEQ * HD;

    const int lr = tid >> 2;        // 0..31 (E loads)
    const int lc = (tid & 3) * 4;
    const int vr = tid >> 4;        // 0..7  (V loads)
    const int vc = (tid & 15) * 4;

    u64 acc[8][4];
    #pragma unroll
    for (int m = 0; m < 8; m++)
        #pragma unroll
        for (int n = 0; n < 4; n++) acc[m][n] = 0ULL;

    float4 pe[4], pv[2];
    #pragma unroll
    for (int p = 0; p < 4; p++)
        pe[p] = *(const float4*)&E[(size_t)(i0 + lr + 32*p) * SEQ + lc];
    #pragma unroll
    for (int p = 0; p < 2; p++)
        pv[p] = *(const float4*)&V[(size_t)(vr + 8*p) * HD + vc];

    for (int kt = 0; kt < SEQ/16; kt++) {
        #pragma unroll
        for (int p = 0; p < 4; p++) {
            Es[lc+0][lr+32*p] = pe[p].x;
            Es[lc+1][lr+32*p] = pe[p].y;
            Es[lc+2][lr+32*p] = pe[p].z;
            Es[lc+3][lr+32*p] = pe[p].w;
        }
        #pragma unroll
        for (int p = 0; p < 2; p++)
            *(float4*)&Vs[vr+8*p][vc] = pv[p];
        __syncthreads();
        if (kt + 1 < SEQ/16) {
            const int c = (kt+1)*16;
            #pragma unroll
            for (int p = 0; p < 4; p++)
                pe[p] = *(const float4*)&E[(size_t)(i0 + lr + 32*p) * SEQ + c + lc];
            #pragma unroll
            for (int p = 0; p < 2; p++)
                pv[p] = *(const float4*)&V[(size_t)(c + vr + 8*p) * HD + vc];
        }
        #pragma unroll
        for (int kk = 0; kk < 16; kk++) {
            float4 a0 = *(const float4*)&Es[kk][ty*8];
            float4 a1 = *(const float4*)&Es[kk][ty*8+4];
            u64 b0 = *(const u64*)&Vs[kk][tx*8+0];
            u64 b1 = *(const u64*)&Vs[kk][tx*8+2];
            u64 b2 = *(const u64*)&Vs[kk][tx*8+4];
            u64 b3 = *(const u64*)&Vs[kk][tx*8+6];
            float am[8] = {a0.x,a0.y,a0.z,a0.w,a1.x,a1.y,a1.z,a1.w};
            #pragma unroll
            for (int m = 0; m < 8; m++) {
                u64 aa = pk2(am[m], am[m]);
                fma2(acc[m][0], aa, b0);
                fma2(acc[m][1], aa, b1);
                fma2(acc[m][2], aa, b2);
                fma2(acc[m][3], aa, b3);
            }
        }
        __syncthreads();
    }

    // write out, tiled 16x across heads (all heads identical)
    #pragma unroll
    for (int m = 0; m < 8; m++) {
        const size_t row = (size_t)b * SEQ + i0 + ty*8 + m;
        float2 c0 = up2(acc[m][0]);
        float2 c1 = up2(acc[m][1]);
        float2 c2 = up2(acc[m][2]);
        float2 c3 = up2(acc[m][3]);
        float4 o0 = make_float4(c0.x, c0.y, c1.x, c1.y);
        float4 o1 = make_float4(c2.x, c2.y, c3.x, c3.y);
        const size_t base = row * (size_t)(HD*16) + tx*8;
        #pragma unroll
        for (int h = 0; h < 16; h++) {
            *(float4*)&Out[base + h*HD]     = o0;
            *(float4*)&Out[base + h*HD + 4] = o1;
        }
    }
}

extern "C" void kernel_launch(void* const* d_in, const int* in_sizes, int n_in,
                              void* d_out, int out_size)
{
    const float* x  = (const float*)d_in[0];
    const float* Wq = (const float*)d_in[1];
    const float* Wk = (const float*)d_in[2];
    const float* Wv = (const float*)d_in[3];
    float* out = (float*)d_out;

    qkv_kernel<<<dim3(NROWS/128, 3), 128>>>(x, Wq, Wk, Wv);
    scores_kernel<<<dim3(SEQ/128, SEQ/128, BATCH), 256>>>();
    expsum_kernel<<<dim3(SEQ/256, BATCH, 4), 256>>>();
    vscale_kernel<<<dim3((NROWS*HD)/256), 256>>>();
    pv_kernel<<<dim3(SEQ/128, 1, BATCH), 128>>>(out);
}

// round 4
// speedup vs baseline: 2.4120x; 2.4098x over previous
#include <cuda_runtime.h>
#include <cuda_bf16.h>

#define BATCH 8
#define SEQ   2048
#define EMB   1024
#define HD    64
#define NROWS (BATCH*SEQ)   // 16384

typedef unsigned int u32;
typedef unsigned long long u64;

// ================= device scratch (allocation-free rule) =================
__device__ __nv_bfloat16 g_qh[NROWS*HD], g_ql[NROWS*HD];
__device__ __nv_bfloat16 g_kh[NROWS*HD], g_kl[NROWS*HD];
__device__ float         g_vf[NROWS*HD];
__device__ __nv_bfloat16 g_vth[BATCH*HD*SEQ], g_vtl[BATCH*HD*SEQ];  // [b][d][j]
__device__ __nv_bfloat16 g_eh[(size_t)BATCH*SEQ*SEQ];               // 64MB
__device__ __nv_bfloat16 g_el[(size_t)BATCH*SEQ*SEQ];               // 64MB
__device__ float         g_Dp[16][NROWS];                           // col-sum partials

// ================= helpers =================
__device__ __forceinline__ u32 smem_to_u32(const void* p) {
    u32 a;
    asm("{ .reg .u64 t; cvta.to.shared.u64 t, %1; cvt.u32.u64 %0, t; }" : "=r"(a) : "l"(p));
    return a;
}
__device__ __forceinline__ u32 swz(u32 off) { return off ^ ((off >> 3) & 0x70); }
__device__ __forceinline__ float bfhi(float x) {
    return __bfloat162float(__float2bfloat16_rn(x));
}
__device__ __forceinline__ u32 pkbf(float a, float b) {
    __nv_bfloat162 t = __floats2bfloat162_rn(a, b);
    return *reinterpret_cast<u32*>(&t);
}

__device__ __forceinline__ void ldmx4(u32* r, u32 addr) {
    asm volatile("ldmatrix.sync.aligned.m8n8.x4.shared.b16 {%0,%1,%2,%3}, [%4];"
        : "=r"(r[0]), "=r"(r[1]), "=r"(r[2]), "=r"(r[3]) : "r"(addr));
}
__device__ __forceinline__ void mma16816(float* d, const u32* a, const u32* b) {
    asm volatile("mma.sync.aligned.m16n8k16.row.col.f32.bf16.bf16.f32 "
        "{%0,%1,%2,%3}, {%4,%5,%6,%7}, {%8,%9}, {%0,%1,%2,%3};"
        : "+f"(d[0]), "+f"(d[1]), "+f"(d[2]), "+f"(d[3])
        : "r"(a[0]), "r"(a[1]), "r"(a[2]), "r"(a[3]), "r"(b[0]), "r"(b[1]));
}
// A-operand ldmatrix address (row-major [m][k], 64-elem/128B rows, swizzled)
__device__ __forceinline__ u32 a_addr(u32 base, int row0, int k0, int lane) {
    int row = row0 + (lane & 15);
    int kb  = k0 + ((lane >> 4) << 3);
    return base + swz((u32)(row * 128 + kb * 2));
}
// B-operand pair ldmatrix address (storage [n][k] = col-major for mma): 2 n-tiles
__device__ __forceinline__ u32 b_addr(u32 base, int n0, int k0, int lane) {
    int n  = n0 + (lane & 7) + ((lane & 16) >> 1);
    int kb = k0 + (lane & 8);
    return base + swz((u32)(n * 128 + kb * 2));
}
// split-store a float4 (4 fp32) as 4 bf16 hi + 4 bf16 lo
__device__ __forceinline__ void split_st(char* hp, char* lp, u32 off, float4 v) {
    float hx = bfhi(v.x), hy = bfhi(v.y), hz = bfhi(v.z), hw = bfhi(v.w);
    *reinterpret_cast<uint2*>(hp + off) = make_uint2(pkbf(hx, hy), pkbf(hz, hw));
    *reinterpret_cast<uint2*>(lp + off) = make_uint2(pkbf(v.x - hx, v.y - hy), pkbf(v.z - hz, v.w - hw));
}
__device__ __forceinline__ void cpa16(u32 dst, const void* src) {
    asm volatile("cp.async.cg.shared.global [%0], [%1], 16;" :: "r"(dst), "l"(src) : "memory");
}
#define CP_COMMIT() asm volatile("cp.async.commit_group;" ::: "memory")
#define CP_WAIT(n)  asm volatile("cp.async.wait_group %0;" :: "n"(n) : "memory")

// ====================================================================
// K1: fused QKV GEMM.  [16384,192] = X[16384,1024] @ Wstack[192,1024]^T
// BM=128, BN=192, k-chunk=64, 256 thr, 8 warps (4m x 2n), warp=32x96.
// 4-term bf16 split (hh+hl+lh+ll). grid = 128.
// ====================================================================
#define QKV_STAGE 81920
#define QKV_SMEM  (2*QKV_STAGE)   // 160 KB

__global__ void __launch_bounds__(256, 1) qkv_kernel(
    const float* __restrict__ X, const float* __restrict__ Wq,
    const float* __restrict__ Wk, const float* __restrict__ Wv)
{
    extern __shared__ char smem[];
    const u32 sb = smem_to_u32(smem);
    const int tid = threadIdx.x, lane = tid & 31, w = tid >> 5;
    const int wm = w & 3, wn = w >> 2;
    const int m0 = blockIdx.x * 128;

    float acc[2][12][4];
    #pragma unroll
    for (int a = 0; a < 2; a++)
        #pragma unroll
        for (int n = 0; n < 12; n++)
            #pragma unroll
            for (int i = 0; i < 4; i++) acc[a][n][i] = 0.0f;

    for (int c = 0; c < EMB / 64; c++) {
        const int k0g = c * 64;
        char* buf = smem + (c & 1) * QKV_STAGE;
        // X tile 128x64 fp32 -> Xh(+0)/Xl(+16384)
        #pragma unroll
        for (int it = 0; it < 8; it++) {
            int idx = tid + it * 256, r = idx >> 4, q = idx & 15;
            float4 v = *reinterpret_cast<const float4*>(X + (size_t)(m0 + r) * EMB + k0g + q * 4);
            split_st(buf, buf + 16384, swz((u32)(r * 128 + q * 8)), v);
        }
        // W tile 192x64 fp32 -> Wh(+32768)/Wl(+57344)
        #pragma unroll
        for (int it = 0; it < 12; it++) {
            int idx = tid + it * 256, r = idx >> 4, q = idx & 15;
            const float* wr = (r < 64)  ? Wq + (size_t)r * EMB
                            : (r < 128) ? Wk + (size_t)(r - 64) * EMB
                                        : Wv + (size_t)(r - 128) * EMB;
            float4 v = *reinterpret_cast<const float4*>(wr + k0g + q * 4);
            split_st(buf + 32768, buf + 57344, swz((u32)(r * 128 + q * 8)), v);
        }
        __syncthreads();
        const u32 xh = sb + (c & 1) * QKV_STAGE, xl = xh + 16384;
        const u32 wh = xh + 32768, wl = xh + 57344;
        #pragma unroll
        for (int ks = 0; ks < 4; ks++) {
            const int kk = ks * 16;
            u32 ah[2][4], al[2][4];
            ldmx4(ah[0], a_addr(xh, wm * 32,      kk, lane));
            ldmx4(ah[1], a_addr(xh, wm * 32 + 16, kk, lane));
            ldmx4(al[0], a_addr(xl, wm * 32,      kk, lane));
            ldmx4(al[1], a_addr(xl, wm * 32 + 16, kk, lane));
            #pragma unroll
            for (int np = 0; np < 6; np++) {
                u32 bh[4], bl[4];
                ldmx4(bh, b_addr(wh, wn * 96 + np * 16, kk, lane));
                ldmx4(bl, b_addr(wl, wn * 96 + np * 16, kk, lane));
                #pragma unroll
                for (int mt = 0; mt < 2; mt++) {
                    mma16816(acc[mt][2*np],   ah[mt], bh);
                    mma16816(acc[mt][2*np],   ah[mt], bl);
                    mma16816(acc[mt][2*np],   al[mt], bh);
                    mma16816(acc[mt][2*np],   al[mt], bl);
                    mma16816(acc[mt][2*np+1], ah[mt], bh + 2);
                    mma16816(acc[mt][2*np+1], ah[mt], bl + 2);
                    mma16816(acc[mt][2*np+1], al[mt], bh + 2);
                    mma16816(acc[mt][2*np+1], al[mt], bl + 2);
                }
            }
        }
        __syncthreads();
    }

    // epilogue: cols <64 -> Q (split), <128 -> K (split), else V (fp32)
    #pragma unroll
    for (int mt = 0; mt < 2; mt++) {
        #pragma unroll
        for (int nt = 0; nt < 12; nt++) {
            const int col = wn * 96 + nt * 8 + 2 * (lane & 3);
            const int r0  = m0 + wm * 32 + mt * 16 + (lane >> 2);
            const float* f = acc[mt][nt];
            #pragma unroll
            for (int half = 0; half < 2; half++) {
                const int row = r0 + 8 * half;
                const float x0 = f[2*half], x1 = f[2*half + 1];
                if (col < 64) {
                    float h0 = bfhi(x0), h1 = bfhi(x1);
                    *reinterpret_cast<u32*>(g_qh + (size_t)row * HD + col) = pkbf(h0, h1);
                    *reinterpret_cast<u32*>(g_ql + (size_t)row * HD + col) = pkbf(x0 - h0, x1 - h1);
                } else if (col < 128) {
                    float h0 = bfhi(x0), h1 = bfhi(x1);
                    *reinterpret_cast<u32*>(g_kh + (size_t)row * HD + col - 64) = pkbf(h0, h1);
                    *reinterpret_cast<u32*>(g_kl + (size_t)row * HD + col - 64) = pkbf(x0 - h0, x1 - h1);
                } else {
                    *reinterpret_cast<float2*>(g_vf + (size_t)row * HD + col - 128) = make_float2(x0, x1);
                }
            }
        }
    }
}

// ====================================================================
// K2: scores tile [128 x 128] = Q @ K^T (3-term), epilogue: exp, col-sum
// partials (softmax over QUERY axis), bf16 split, staged coalesced store.
// grid = (16 j, 16 i, 8 b), 256 thr, warps 4m x 2n (warp 32x64).
// ====================================================================
#define SCR_SMEM (65536 + 2048)

__global__ void __launch_bounds__(256, 2) scores_kernel()
{
    extern __shared__ char smem[];
    const u32 sb = smem_to_u32(smem);
    const int tid = threadIdx.x, lane = tid & 31, w = tid >> 5;
    const int wm = w & 3, wn = w >> 2;
    const int b = blockIdx.z, i0 = blockIdx.y * 128, j0 = blockIdx.x * 128;

    // load Qh/Ql/Kh/Kl tiles (each 128 rows x 64 bf16)
    {
        const __nv_bfloat16* srcs[4] = {
            g_qh + ((size_t)b * SEQ + i0) * HD, g_ql + ((size_t)b * SEQ + i0) * HD,
            g_kh + ((size_t)b * SEQ + j0) * HD, g_kl + ((size_t)b * SEQ + j0) * HD };
        #pragma unroll
        for (int s = 0; s < 4; s++) {
            const __nv_bfloat16* sp = srcs[s];
            char* dp = smem + s * 16384;
            #pragma unroll
            for (int it = 0; it < 4; it++) {
                int idx = tid + it * 256, r = idx >> 3, u = idx & 7;
                *reinterpret_cast<uint4*>(dp + swz((u32)(r * 128 + u * 16))) =
                    *reinterpret_cast<const uint4*>(sp + (size_t)r * HD + u * 8);
            }
        }
    }
    __syncthreads();

    float acc[2][8][4];
    #pragma unroll
    for (int a = 0; a < 2; a++)
        #pragma unroll
        for (int n = 0; n < 8; n++)
            #pragma unroll
            for (int i = 0; i < 4; i++) acc[a][n][i] = 0.0f;

    const u32 qh = sb, ql = sb + 16384, kh = sb + 32768, kl = sb + 49152;
    #pragma unroll
    for (int ks = 0; ks < 4; ks++) {
        const int kk = ks * 16;
        u32 ah[2][4], al[2][4];
        ldmx4(ah[0], a_addr(qh, wm * 32,      kk, lane));
        ldmx4(ah[1], a_addr(qh, wm * 32 + 16, kk, lane));
        ldmx4(al[0], a_addr(ql, wm * 32,      kk, lane));
        ldmx4(al[1], a_addr(ql, wm * 32 + 16, kk, lane));
        #pragma unroll
        for (int np = 0; np < 4; np++) {
            u32 bh[4], bl[4];
            ldmx4(bh, b_addr(kh, wn * 64 + np * 16, kk, lane));
            ldmx4(bl, b_addr(kl, wn * 64 + np * 16, kk, lane));
            #pragma unroll
            for (int mt = 0; mt < 2; mt++) {
                mma16816(acc[mt][2*np],   ah[mt], bh);
                mma16816(acc[mt][2*np],   ah[mt], bl);
                mma16816(acc[mt][2*np],   al[mt], bh);
                mma16816(acc[mt][2*np+1], ah[mt], bh + 2);
                mma16816(acc[mt][2*np+1], ah[mt], bl + 2);
                mma16816(acc[mt][2*np+1], al[mt], bh + 2);
            }
        }
    }

    // exp in place
    #pragma unroll
    for (int mt = 0; mt < 2; mt++)
        #pragma unroll
        for (int nt = 0; nt < 8; nt++)
            #pragma unroll
            for (int i = 0; i < 4; i++)
                acc[mt][nt][i] = __expf(acc[mt][nt][i]);

    // column-sum partials (over the 32 rows this warp owns), deterministic
    float* csm = reinterpret_cast<float*>(smem + 65536);   // [4][128]
    {
        float cs[8][2];
        #pragma unroll
        for (int nt = 0; nt < 8; nt++) {
            #pragma unroll
            for (int cc = 0; cc < 2; cc++) {
                float v = acc[0][nt][cc] + acc[0][nt][cc+2] + acc[1][nt][cc] + acc[1][nt][cc+2];
                v += __shfl_xor_sync(0xffffffffu, v, 4);
                v += __shfl_xor_sync(0xffffffffu, v, 8);
                v += __shfl_xor_sync(0xffffffffu, v, 16);
                cs[nt][cc] = v;
            }
        }
        if (lane < 4) {
            #pragma unroll
            for (int nt = 0; nt < 8; nt++)
                *reinterpret_cast<float2*>(&csm[wm * 128 + wn * 64 + nt * 8 + 2 * lane]) =
                    make_float2(cs[nt][0], cs[nt][1]);
        }
    }
    __syncthreads();   // operands fully consumed; colsum partials visible

    // stage split E into smem (Eh at 0, El at 32768), plus g_Dp reduce
    #pragma unroll
    for (int mt = 0; mt < 2; mt++) {
        #pragma unroll
        for (int nt = 0; nt < 8; nt++) {
            const int colp = wn * 64 + nt * 8 + 2 * (lane & 3);
            #pragma unroll
            for (int half = 0; half < 2; half++) {
                const int row = wm * 32 + mt * 16 + (lane >> 2) + 8 * half;
                const float x0 = acc[mt][nt][2*half], x1 = acc[mt][nt][2*half + 1];
                const float h0 = bfhi(x0), h1 = bfhi(x1);
                const u32 off = swz((u32)(row * 256 + colp * 2));
                *reinterpret_cast<u32*>(smem + off)         = pkbf(h0, h1);
                *reinterpret_cast<u32*>(smem + 32768 + off) = pkbf(x0 - h0, x1 - h1);
            }
        }
    }
    if (tid < 128) {
        float s = csm[tid] + csm[128 + tid] + csm[256 + tid] + csm[384 + tid];
        g_Dp[blockIdx.y][b * SEQ + j0 + tid] = s;
    }
    __syncthreads();

    // coalesced copy-out
    const size_t ebase = ((size_t)b * SEQ + i0) * SEQ + j0;
    #pragma unroll
    for (int it = 0; it < 8; it++) {
        int u = tid + it * 256, r = u >> 4, cu = u & 15;
        uint4 vh = *reinterpret_cast<const uint4*>(smem + swz((u32)(u * 16)));
        uint4 vl = *reinterpret_cast<const uint4*>(smem + 32768 + swz((u32)(u * 16)));
        *reinterpret_cast<uint4*>(g_eh + ebase + (size_t)r * SEQ + cu * 8) = vh;
        *reinterpret_cast<uint4*>(g_el + ebase + (size_t)r * SEQ + cu * 8) = vl;
    }
}

// ====================================================================
// K3: V' = V / D, transpose to [b][d][j], split bf16.
// ====================================================================
__global__ void __launch_bounds__(256) vscale_kernel()
{
    const int t = blockIdx.x * 256 + threadIdx.x;    // = b*SEQ + j
    float D = 0.0f;
    #pragma unroll
    for (int p = 0; p < 16; p++) D += g_Dp[p][t];
    const float dinv = 1.0f / D;
    const int b = t >> 11, j = t & (SEQ - 1);
    const float* vr = g_vf + (size_t)t * HD;
    #pragma unroll 8
    for (int d = 0; d < HD; d++) {
        float x = vr[d] * dinv;
        float h = bfhi(x);
        g_vth[((size_t)b * HD + d) * SEQ + j] = __float2bfloat16_rn(x);
        g_vtl[((size_t)b * HD + d) * SEQ + j] = __float2bfloat16_rn(x - h);
    }
}

// ====================================================================
// K5: O[b] = E[b] @ V'[b]^T-layout, cp.async double-buffered, out x16 heads.
// BM=128, BN=64, k-chunk=64, grid (16, 8), warps 4m x 2n (warp 32x32).
// ====================================================================
#define PV_STAGE 49152
#define PV_SMEM  (2*PV_STAGE)    // 96 KB

__global__ void __launch_bounds__(256, 2) pv_kernel(float* __restrict__ Out)
{
    extern __shared__ char smem[];
    const u32 sb = smem_to_u32(smem);
    const int tid = threadIdx.x, lane = tid & 31, w = tid >> 5;
    const int wm = w & 3, wn = w >> 2;
    const int b = blockIdx.y, i0 = blockIdx.x * 128;

    auto issue = [&](int c) {
        const u32 base = sb + (c & 1) * PV_STAGE;
        const int k0 = c * 64;
        #pragma unroll
        for (int it = 0; it < 4; it++) {       // Eh/El: 128 rows x 4 x16B
            int idx = tid + it * 256, r = idx >> 3, u = idx & 7;
            size_t so = ((size_t)b * SEQ + i0 + r) * SEQ + k0 + u * 8;
            u32 d = base + swz((u32)(r * 128 + u * 16));
            cpa16(d,         g_eh + so);
            cpa16(d + 16384, g_el + so);
        }
        #pragma unroll
        for (int it = 0; it < 2; it++) {       // Vh/Vl: 64 rows
            int idx = tid + it * 256, r = idx >> 3, u = idx & 7;
            size_t so = ((size_t)b * HD + r) * SEQ + k0 + u * 8;
            u32 d = base + 32768 + swz((u32)(r * 128 + u * 16));
            cpa16(d,        g_vth + so);
            cpa16(d + 8192, g_vtl + so);
        }
    };

    float acc[2][4][4];
    #pragma unroll
    for (int a = 0; a < 2; a++)
        #pragma unroll
        for (int n = 0; n < 4; n++)
            #pragma unroll
            for (int i = 0; i < 4; i++) acc[a][n][i] = 0.0f;

    issue(0); CP_COMMIT();
    const int NC = SEQ / 64;   // 32
    for (int c = 0; c < NC; c++) {
        if (c + 1 < NC) { issue(c + 1); CP_COMMIT(); CP_WAIT(1); }
        else            { CP_WAIT(0); }
        __syncthreads();
        const u32 eh = sb + (c & 1) * PV_STAGE, el = eh + 16384;
        const u32 vh = eh + 32768, vl = eh + 40960;
        #pragma unroll
        for (int ks = 0; ks < 4; ks++) {
            const int kk = ks * 16;
            u32 ah[2][4], al[2][4];
            ldmx4(ah[0], a_addr(eh, wm * 32,      kk, lane));
            ldmx4(ah[1], a_addr(eh, wm * 32 + 16, kk, lane));
            ldmx4(al[0], a_addr(el, wm * 32,      kk, lane));
            ldmx4(al[1], a_addr(el, wm * 32 + 16, kk, lane));
            #pragma unroll
            for (int np = 0; np < 2; np++) {
                u32 bh[4], bl[4];
                ldmx4(bh, b_addr(vh, wn * 32 + np * 16, kk, lane));
                ldmx4(bl, b_addr(vl, wn * 32 + np * 16, kk, lane));
                #pragma unroll
                for (int mt = 0; mt < 2; mt++) {
                    mma16816(acc[mt][2*np],   ah[mt], bh);
                    mma16816(acc[mt][2*np],   ah[mt], bl);
                    mma16816(acc[mt][2*np],   al[mt], bh);
                    mma16816(acc[mt][2*np+1], ah[mt], bh + 2);
                    mma16816(acc[mt][2*np+1], ah[mt], bl + 2);
                    mma16816(acc[mt][2*np+1], al[mt], bh + 2);
                }
            }
        }
        __syncthreads();
    }

    // epilogue: write result tiled x16 across heads
    #pragma unroll
    for (int mt = 0; mt < 2; mt++) {
        #pragma unroll
        for (int nt = 0; nt < 4; nt++) {
            const int col = wn * 32 + nt * 8 + 2 * (lane & 3);
            #pragma unroll
            for (int half = 0; half < 2; half++) {
                const int row = i0 + wm * 32 + mt * 16 + (lane >> 2) + 8 * half;
                float2 v = make_float2(acc[mt][nt][2*half], acc[mt][nt][2*half + 1]);
                float* orow = Out + ((size_t)b * SEQ + row) * (size_t)(HD * 16) + col;
                #pragma unroll
                for (int h = 0; h < 16; h++)
                    *reinterpret_cast<float2*>(orow + h * HD) = v;
            }
        }
    }
}

// ====================================================================
extern "C" void kernel_launch(void* const* d_in, const int* in_sizes, int n_in,
                              void* d_out, int out_size)
{
    const float* x  = (const float*)d_in[0];
    const float* Wq = (const float*)d_in[1];
    const float* Wk = (const float*)d_in[2];
    const float* Wv = (const float*)d_in[3];
    float* out = (float*)d_out;

    cudaFuncSetAttribute(qkv_kernel,    cudaFuncAttributeMaxDynamicSharedMemorySize, QKV_SMEM);
    cudaFuncSetAttribute(scores_kernel, cudaFuncAttributeMaxDynamicSharedMemorySize, SCR_SMEM);
    cudaFuncSetAttribute(pv_kernel,     cudaFuncAttributeMaxDynamicSharedMemorySize, PV_SMEM);

    qkv_kernel<<<NROWS/128, 256, QKV_SMEM>>>(x, Wq, Wk, Wv);
    scores_kernel<<<dim3(SEQ/128, SEQ/128, BATCH), 256, SCR_SMEM>>>();
    vscale_kernel<<<NROWS/256, 256>>>();
    pv_kernel<<<dim3(SEQ/128, BATCH), 256, PV_SMEM>>>(out);
}

// round 5
// speedup vs baseline: 2.6342x; 1.0922x over previous
#include <cuda_runtime.h>
#include <cuda_bf16.h>

#define BATCH 8
#define SEQ   2048
#define EMB   1024
#define HD    64
#define NROWS (BATCH*SEQ)   // 16384

typedef unsigned int u32;
typedef unsigned long long u64;

// ================= device scratch (allocation-free rule) =================
__device__ __nv_bfloat16 g_xh[(size_t)NROWS*EMB], g_xl[(size_t)NROWS*EMB];  // 32MB each
__device__ __nv_bfloat16 g_wh[192*EMB], g_wl[192*EMB];
__device__ __nv_bfloat16 g_qh[NROWS*HD], g_ql[NROWS*HD];
__device__ __nv_bfloat16 g_kh[NROWS*HD], g_kl[NROWS*HD];
__device__ float         g_vf[NROWS*HD];
__device__ __nv_bfloat16 g_vth[BATCH*HD*SEQ], g_vtl[BATCH*HD*SEQ];  // [b][d][j]
__device__ __nv_bfloat16 g_eh[(size_t)BATCH*SEQ*SEQ];               // 64MB
__device__ __nv_bfloat16 g_el[(size_t)BATCH*SEQ*SEQ];               // 64MB
__device__ float         g_Dp[16][NROWS];                           // col-sum partials
__device__ float         g_po[2][(size_t)NROWS*HD];                 // pv split-j partials

// ================= helpers =================
__device__ __forceinline__ u32 smem_to_u32(const void* p) {
    u32 a;
    asm("{ .reg .u64 t; cvta.to.shared.u64 t, %1; cvt.u32.u64 %0, t; }" : "=r"(a) : "l"(p));
    return a;
}
__device__ __forceinline__ u32 swz(u32 off) { return off ^ ((off >> 3) & 0x70); }
__device__ __forceinline__ float bfhi(float x) {
    return __bfloat162float(__float2bfloat16_rn(x));
}
__device__ __forceinline__ u32 pkbf(float a, float b) {
    __nv_bfloat162 t = __floats2bfloat162_rn(a, b);
    return *reinterpret_cast<u32*>(&t);
}
__device__ __forceinline__ void ldmx4(u32* r, u32 addr) {
    asm volatile("ldmatrix.sync.aligned.m8n8.x4.shared.b16 {%0,%1,%2,%3}, [%4];"
        : "=r"(r[0]), "=r"(r[1]), "=r"(r[2]), "=r"(r[3]) : "r"(addr));
}
__device__ __forceinline__ void mma16816(float* d, const u32* a, const u32* b) {
    asm volatile("mma.sync.aligned.m16n8k16.row.col.f32.bf16.bf16.f32 "
        "{%0,%1,%2,%3}, {%4,%5,%6,%7}, {%8,%9}, {%0,%1,%2,%3};"
        : "+f"(d[0]), "+f"(d[1]), "+f"(d[2]), "+f"(d[3])
        : "r"(a[0]), "r"(a[1]), "r"(a[2]), "r"(a[3]), "r"(b[0]), "r"(b[1]));
}
__device__ __forceinline__ u32 a_addr(u32 base, int row0, int k0, int lane) {
    int row = row0 + (lane & 15);
    int kb  = k0 + ((lane >> 4) << 3);
    return base + swz((u32)(row * 128 + kb * 2));
}
__device__ __forceinline__ u32 b_addr(u32 base, int n0, int k0, int lane) {
    int n  = n0 + (lane & 7) + ((lane & 16) >> 1);
    int kb = k0 + (lane & 8);
    return base + swz((u32)(n * 128 + kb * 2));
}
__device__ __forceinline__ void cpa16(u32 dst, const void* src) {
    asm volatile("cp.async.cg.shared.global [%0], [%1], 16;" :: "r"(dst), "l"(src) : "memory");
}
#define CP_COMMIT() asm volatile("cp.async.commit_group;" ::: "memory")
#define CP_WAIT(n)  asm volatile("cp.async.wait_group %0;" :: "n"(n) : "memory")

// ====================================================================
// K0: split X and stacked W into bf16 hi/lo (one pass).
// grid = 8192 (X) + 96 (W) blocks of 256; 8 elems/thread.
// ====================================================================
__global__ void __launch_bounds__(256) split_kernel(
    const float* __restrict__ X, const float* __restrict__ Wq,
    const float* __restrict__ Wk, const float* __restrict__ Wv)
{
    const int bx = blockIdx.x;
    if (bx < 8192) {
        size_t e0 = ((size_t)bx * 256 + threadIdx.x) * 8;
        float4 v0 = *reinterpret_cast<const float4*>(X + e0);
        float4 v1 = *reinterpret_cast<const float4*>(X + e0 + 4);
        float xs[8] = {v0.x, v0.y, v0.z, v0.w, v1.x, v1.y, v1.z, v1.w};
        u32 hb[4], lb[4];
        #pragma unroll
        for (int i = 0; i < 4; i++) {
            float h0 = bfhi(xs[2*i]), h1 = bfhi(xs[2*i+1]);
            hb[i] = pkbf(h0, h1);
            lb[i] = pkbf(xs[2*i] - h0, xs[2*i+1] - h1);
        }
        *reinterpret_cast<uint4*>(g_xh + e0) = make_uint4(hb[0], hb[1], hb[2], hb[3]);
        *reinterpret_cast<uint4*>(g_xl + e0) = make_uint4(lb[0], lb[1], lb[2], lb[3]);
    } else {
        size_t e0 = ((size_t)(bx - 8192) * 256 + threadIdx.x) * 8;
        int r = (int)(e0 >> 10), c = (int)(e0 & 1023);
        const float* wr = (r < 64)  ? Wq + (size_t)r * EMB
                        : (r < 128) ? Wk + (size_t)(r - 64) * EMB
                                    : Wv + (size_t)(r - 128) * EMB;
        float4 v0 = *reinterpret_cast<const float4*>(wr + c);
        float4 v1 = *reinterpret_cast<const float4*>(wr + c + 4);
        float xs[8] = {v0.x, v0.y, v0.z, v0.w, v1.x, v1.y, v1.z, v1.w};
        u32 hb[4], lb[4];
        #pragma unroll
        for (int i = 0; i < 4; i++) {
            float h0 = bfhi(xs[2*i]), h1 = bfhi(xs[2*i+1]);
            hb[i] = pkbf(h0, h1);
            lb[i] = pkbf(xs[2*i] - h0, xs[2*i+1] - h1);
        }
        *reinterpret_cast<uint4*>(g_wh + e0) = make_uint4(hb[0], hb[1], hb[2], hb[3]);
        *reinterpret_cast<uint4*>(g_wl + e0) = make_uint4(lb[0], lb[1], lb[2], lb[3]);
    }
}

// ====================================================================
// K1: fused QKV GEMM.  [16384,192] = X[16384,1024] @ Wstack[192,1024]^T
// BM=128, BN=192, k-chunk=64, 256 thr, warps 4m x 2n (warp 32x96).
// 3-term bf16 split, cp.async double-buffered. grid = 128.
// ====================================================================
#define QKV_STAGE 81920
#define QKV_SMEM  (2*QKV_STAGE)   // 160 KB

__global__ void __launch_bounds__(256, 1) qkv_kernel()
{
    extern __shared__ char smem[];
    const u32 sb = smem_to_u32(smem);
    const int tid = threadIdx.x, lane = tid & 31, w = tid >> 5;
    const int wm = w & 3, wn = w >> 2;
    const int m0 = blockIdx.x * 128;

    auto issue = [&](int c) {
        const u32 base = sb + (c & 1) * QKV_STAGE;
        const int k0 = c * 64;
        #pragma unroll
        for (int it = 0; it < 4; it++) {        // Xh / Xl: 128 rows
            int idx = tid + it * 256, r = idx >> 3, u = idx & 7;
            size_t so = (size_t)(m0 + r) * EMB + k0 + u * 8;
            u32 d = base + swz((u32)(r * 128 + u * 16));
            cpa16(d,         g_xh + so);
            cpa16(d + 16384, g_xl + so);
        }
        #pragma unroll
        for (int it = 0; it < 6; it++) {        // Wh / Wl: 192 rows
            int idx = tid + it * 256, r = idx >> 3, u = idx & 7;
            size_t so = (size_t)r * EMB + k0 + u * 8;
            u32 d = base + 32768 + swz((u32)(r * 128 + u * 16));
            cpa16(d,         g_wh + so);
            cpa16(d + 24576, g_wl + so);
        }
    };

    float acc[2][12][4];
    #pragma unroll
    for (int a = 0; a < 2; a++)
        #pragma unroll
        for (int n = 0; n < 12; n++)
            #pragma unroll
            for (int i = 0; i < 4; i++) acc[a][n][i] = 0.0f;

    issue(0); CP_COMMIT();
    const int NC = EMB / 64;   // 16
    for (int c = 0; c < NC; c++) {
        if (c + 1 < NC) { issue(c + 1); CP_COMMIT(); CP_WAIT(1); }
        else            { CP_WAIT(0); }
        __syncthreads();
        const u32 xh = sb + (c & 1) * QKV_STAGE, xl = xh + 16384;
        const u32 wh = xh + 32768, wl = xh + 57344;
        #pragma unroll
        for (int ks = 0; ks < 4; ks++) {
            const int kk = ks * 16;
            u32 ah[2][4], al[2][4];
            ldmx4(ah[0], a_addr(xh, wm * 32,      kk, lane));
            ldmx4(ah[1], a_addr(xh, wm * 32 + 16, kk, lane));
            ldmx4(al[0], a_addr(xl, wm * 32,      kk, lane));
            ldmx4(al[1], a_addr(xl, wm * 32 + 16, kk, lane));
            #pragma unroll
            for (int np = 0; np < 6; np++) {
                u32 bh[4], bl[4];
                ldmx4(bh, b_addr(wh, wn * 96 + np * 16, kk, lane));
                ldmx4(bl, b_addr(wl, wn * 96 + np * 16, kk, lane));
                #pragma unroll
                for (int mt = 0; mt < 2; mt++) {
                    mma16816(acc[mt][2*np],   ah[mt], bh);
                    mma16816(acc[mt][2*np],   ah[mt], bl);
                    mma16816(acc[mt][2*np],   al[mt], bh);
                    mma16816(acc[mt][2*np+1], ah[mt], bh + 2);
                    mma16816(acc[mt][2*np+1], ah[mt], bl + 2);
                    mma16816(acc[mt][2*np+1], al[mt], bh + 2);
                }
            }
        }
        __syncthreads();
    }

    // epilogue: cols <64 -> Q (split), <128 -> K (split), else V (fp32)
    #pragma unroll
    for (int mt = 0; mt < 2; mt++) {
        #pragma unroll
        for (int nt = 0; nt < 12; nt++) {
            const int col = wn * 96 + nt * 8 + 2 * (lane & 3);
            const int r0  = m0 + wm * 32 + mt * 16 + (lane >> 2);
            const float* f = acc[mt][nt];
            #pragma unroll
            for (int half = 0; half < 2; half++) {
                const int row = r0 + 8 * half;
                const float x0 = f[2*half], x1 = f[2*half + 1];
                if (col < 64) {
                    float h0 = bfhi(x0), h1 = bfhi(x1);
                    *reinterpret_cast<u32*>(g_qh + (size_t)row * HD + col) = pkbf(h0, h1);
                    *reinterpret_cast<u32*>(g_ql + (size_t)row * HD + col) = pkbf(x0 - h0, x1 - h1);
                } else if (col < 128) {
                    float h0 = bfhi(x0), h1 = bfhi(x1);
                    *reinterpret_cast<u32*>(g_kh + (size_t)row * HD + col - 64) = pkbf(h0, h1);
                    *reinterpret_cast<u32*>(g_kl + (size_t)row * HD + col - 64) = pkbf(x0 - h0, x1 - h1);
                } else {
                    *reinterpret_cast<float2*>(g_vf + (size_t)row * HD + col - 128) = make_float2(x0, x1);
                }
            }
        }
    }
}

// ====================================================================
// K2: scores tile [128 x 128] = Q @ K^T (3-term), epilogue: exp, col-sum
// partials (softmax over QUERY axis), bf16 split, staged coalesced store.
// grid = (16 j, 16 i, 8 b), 256 thr, warps 4m x 2n (warp 32x64).
// ====================================================================
#define SCR_SMEM (65536 + 2048)

__global__ void __launch_bounds__(256, 2) scores_kernel()
{
    extern __shared__ char smem[];
    const u32 sb = smem_to_u32(smem);
    const int tid = threadIdx.x, lane = tid & 31, w = tid >> 5;
    const int wm = w & 3, wn = w >> 2;
    const int b = blockIdx.z, i0 = blockIdx.y * 128, j0 = blockIdx.x * 128;

    // cp.async load Qh/Ql/Kh/Kl tiles (each 128 rows x 64 bf16)
    {
        const __nv_bfloat16* srcs[4] = {
            g_qh + ((size_t)b * SEQ + i0) * HD, g_ql + ((size_t)b * SEQ + i0) * HD,
            g_kh + ((size_t)b * SEQ + j0) * HD, g_kl + ((size_t)b * SEQ + j0) * HD };
        #pragma unroll
        for (int s = 0; s < 4; s++) {
            #pragma unroll
            for (int it = 0; it < 4; it++) {
                int idx = tid + it * 256, r = idx >> 3, u = idx & 7;
                cpa16(sb + s * 16384 + swz((u32)(r * 128 + u * 16)),
                      srcs[s] + (size_t)r * HD + u * 8);
            }
        }
        CP_COMMIT(); CP_WAIT(0);
    }
    __syncthreads();

    float acc[2][8][4];
    #pragma unroll
    for (int a = 0; a < 2; a++)
        #pragma unroll
        for (int n = 0; n < 8; n++)
            #pragma unroll
            for (int i = 0; i < 4; i++) acc[a][n][i] = 0.0f;

    const u32 qh = sb, ql = sb + 16384, kh = sb + 32768, kl = sb + 49152;
    #pragma unroll
    for (int ks = 0; ks < 4; ks++) {
        const int kk = ks * 16;
        u32 ah[2][4], al[2][4];
        ldmx4(ah[0], a_addr(qh, wm * 32,      kk, lane));
        ldmx4(ah[1], a_addr(qh, wm * 32 + 16, kk, lane));
        ldmx4(al[0], a_addr(ql, wm * 32,      kk, lane));
        ldmx4(al[1], a_addr(ql, wm * 32 + 16, kk, lane));
        #pragma unroll
        for (int np = 0; np < 4; np++) {
            u32 bh[4], bl[4];
            ldmx4(bh, b_addr(kh, wn * 64 + np * 16, kk, lane));
            ldmx4(bl, b_addr(kl, wn * 64 + np * 16, kk, lane));
            #pragma unroll
            for (int mt = 0; mt < 2; mt++) {
                mma16816(acc[mt][2*np],   ah[mt], bh);
                mma16816(acc[mt][2*np],   ah[mt], bl);
                mma16816(acc[mt][2*np],   al[mt], bh);
                mma16816(acc[mt][2*np+1], ah[mt], bh + 2);
                mma16816(acc[mt][2*np+1], ah[mt], bl + 2);
                mma16816(acc[mt][2*np+1], al[mt], bh + 2);
            }
        }
    }

    // exp in place
    #pragma unroll
    for (int mt = 0; mt < 2; mt++)
        #pragma unroll
        for (int nt = 0; nt < 8; nt++)
            #pragma unroll
            for (int i = 0; i < 4; i++)
                acc[mt][nt][i] = __expf(acc[mt][nt][i]);

    // column-sum partials (over the 32 rows this warp owns), deterministic
    float* csm = reinterpret_cast<float*>(smem + 65536);   // [4][128]
    {
        float cs[8][2];
        #pragma unroll
        for (int nt = 0; nt < 8; nt++) {
            #pragma unroll
            for (int cc = 0; cc < 2; cc++) {
                float v = acc[0][nt][cc] + acc[0][nt][cc+2] + acc[1][nt][cc] + acc[1][nt][cc+2];
                v += __shfl_xor_sync(0xffffffffu, v, 4);
                v += __shfl_xor_sync(0xffffffffu, v, 8);
                v += __shfl_xor_sync(0xffffffffu, v, 16);
                cs[nt][cc] = v;
            }
        }
        if (lane < 4) {
            #pragma unroll
            for (int nt = 0; nt < 8; nt++)
                *reinterpret_cast<float2*>(&csm[wm * 128 + wn * 64 + nt * 8 + 2 * lane]) =
                    make_float2(cs[nt][0], cs[nt][1]);
        }
    }
    __syncthreads();   // operands fully consumed; colsum partials visible

    // stage split E into smem (Eh at 0, El at 32768), plus g_Dp reduce
    #pragma unroll
    for (int mt = 0; mt < 2; mt++) {
        #pragma unroll
        for (int nt = 0; nt < 8; nt++) {
            const int colp = wn * 64 + nt * 8 + 2 * (lane & 3);
            #pragma unroll
            for (int half = 0; half < 2; half++) {
                const int row = wm * 32 + mt * 16 + (lane >> 2) + 8 * half;
                const float x0 = acc[mt][nt][2*half], x1 = acc[mt][nt][2*half + 1];
                const float h0 = bfhi(x0), h1 = bfhi(x1);
                const u32 off = swz((u32)(row * 256 + colp * 2));
                *reinterpret_cast<u32*>(smem + off)         = pkbf(h0, h1);
                *reinterpret_cast<u32*>(smem + 32768 + off) = pkbf(x0 - h0, x1 - h1);
            }
        }
    }
    if (tid < 128) {
        float s = csm[tid] + csm[128 + tid] + csm[256 + tid] + csm[384 + tid];
        g_Dp[blockIdx.y][b * SEQ + j0 + tid] = s;
    }
    __syncthreads();

    // coalesced copy-out
    const size_t ebase = ((size_t)b * SEQ + i0) * SEQ + j0;
    #pragma unroll
    for (int it = 0; it < 8; it++) {
        int u = tid + it * 256, r = u >> 4, cu = u & 15;
        uint4 vh = *reinterpret_cast<const uint4*>(smem + swz((u32)(u * 16)));
        uint4 vl = *reinterpret_cast<const uint4*>(smem + 32768 + swz((u32)(u * 16)));
        *reinterpret_cast<uint4*>(g_eh + ebase + (size_t)r * SEQ + cu * 8) = vh;
        *reinterpret_cast<uint4*>(g_el + ebase + (size_t)r * SEQ + cu * 8) = vl;
    }
}

// ====================================================================
// K3: V' = V / D, transpose to [b][d][j], split bf16.
// ====================================================================
__global__ void __launch_bounds__(256) vscale_kernel()
{
    const int t = blockIdx.x * 256 + threadIdx.x;    // = b*SEQ + j
    float D = 0.0f;
    #pragma unroll
    for (int p = 0; p < 16; p++) D += g_Dp[p][t];
    const float dinv = 1.0f / D;
    const int b = t >> 11, j = t & (SEQ - 1);
    const float* vr = g_vf + (size_t)t * HD;
    #pragma unroll 8
    for (int d = 0; d < HD; d++) {
        float x = vr[d] * dinv;
        float h = bfhi(x);
        g_vth[((size_t)b * HD + d) * SEQ + j] = __float2bfloat16_rn(x);
        g_vtl[((size_t)b * HD + d) * SEQ + j] = __float2bfloat16_rn(x - h);
    }
}

// ====================================================================
// K4: pv partials.  po[js] = E[:, js-half] @ V'[js-half, :]
// grid (16 i, 2 js, 8 b), 256 thr, warps 4m x 2n (warp 32x32), chunk 64.
// ====================================================================
#define PV_STAGE 49152
#define PV_SMEM  (2*PV_STAGE)    // 96 KB

__global__ void __launch_bounds__(256, 1) pv_kernel()
{
    extern __shared__ char smem[];
    const u32 sb = smem_to_u32(smem);
    const int tid = threadIdx.x, lane = tid & 31, w = tid >> 5;
    const int wm = w & 3, wn = w >> 2;
    const int b = blockIdx.z, js = blockIdx.y, i0 = blockIdx.x * 128;
    const int jbase = js * (SEQ / 2);

    auto issue = [&](int c) {
        const u32 base = sb + (c & 1) * PV_STAGE;
        const int k0 = jbase + c * 64;
        #pragma unroll
        for (int it = 0; it < 4; it++) {       // Eh/El: 128 rows
            int idx = tid + it * 256, r = idx >> 3, u = idx & 7;
            size_t so = ((size_t)b * SEQ + i0 + r) * SEQ + k0 + u * 8;
            u32 d = base + swz((u32)(r * 128 + u * 16));
            cpa16(d,         g_eh + so);
            cpa16(d + 16384, g_el + so);
        }
        #pragma unroll
        for (int it = 0; it < 2; it++) {       // Vh/Vl: 64 rows
            int idx = tid + it * 256, r = idx >> 3, u = idx & 7;
            size_t so = ((size_t)b * HD + r) * SEQ + k0 + u * 8;
            u32 d = base + 32768 + swz((u32)(r * 128 + u * 16));
            cpa16(d,        g_vth + so);
            cpa16(d + 8192, g_vtl + so);
        }
    };

    float acc[2][4][4];
    #pragma unroll
    for (int a = 0; a < 2; a++)
        #pragma unroll
        for (int n = 0; n < 4; n++)
            #pragma unroll
            for (int i = 0; i < 4; i++) acc[a][n][i] = 0.0f;

    issue(0); CP_COMMIT();
    const int NC = SEQ / 2 / 64;   // 16
    for (int c = 0; c < NC; c++) {
        if (c + 1 < NC) { issue(c + 1); CP_COMMIT(); CP_WAIT(1); }
        else            { CP_WAIT(0); }
        __syncthreads();
        const u32 eh = sb + (c & 1) * PV_STAGE, el = eh + 16384;
        const u32 vh = eh + 32768, vl = eh + 40960;
        #pragma unroll
        for (int ks = 0; ks < 4; ks++) {
            const int kk = ks * 16;
            u32 ah[2][4], al[2][4];
            ldmx4(ah[0], a_addr(eh, wm * 32,      kk, lane));
            ldmx4(ah[1], a_addr(eh, wm * 32 + 16, kk, lane));
            ldmx4(al[0], a_addr(el, wm * 32,      kk, lane));
            ldmx4(al[1], a_addr(el, wm * 32 + 16, kk, lane));
            #pragma unroll
            for (int np = 0; np < 2; np++) {
                u32 bh[4], bl[4];
                ldmx4(bh, b_addr(vh, wn * 32 + np * 16, kk, lane));
                ldmx4(bl, b_addr(vl, wn * 32 + np * 16, kk, lane));
                #pragma unroll
                for (int mt = 0; mt < 2; mt++) {
                    mma16816(acc[mt][2*np],   ah[mt], bh);
                    mma16816(acc[mt][2*np],   ah[mt], bl);
                    mma16816(acc[mt][2*np],   al[mt], bh);
                    mma16816(acc[mt][2*np+1], ah[mt], bh + 2);
                    mma16816(acc[mt][2*np+1], ah[mt], bl + 2);
                    mma16816(acc[mt][2*np+1], al[mt], bh + 2);
                }
            }
        }
        __syncthreads();
    }

    float* po = g_po[js];
    #pragma unroll
    for (int mt = 0; mt < 2; mt++) {
        #pragma unroll
        for (int nt = 0; nt < 4; nt++) {
            const int col = wn * 32 + nt * 8 + 2 * (lane & 3);
            #pragma unroll
            for (int half = 0; half < 2; half++) {
                const int row = i0 + wm * 32 + mt * 16 + (lane >> 2) + 8 * half;
                *reinterpret_cast<float2*>(po + ((size_t)b * SEQ + row) * HD + col) =
                    make_float2(acc[mt][nt][2*half], acc[mt][nt][2*half + 1]);
            }
        }
    }
}

// ====================================================================
// K5: out = (po0 + po1), tiled x16 across heads.
// ====================================================================
__global__ void __launch_bounds__(256) outred_kernel(float* __restrict__ Out)
{
    const int idx = blockIdx.x * 256 + threadIdx.x;   // < NROWS*HD/4
    const size_t e0 = (size_t)idx * 4;
    const int row = idx >> 4, col = (idx & 15) * 4;
    float4 a = *reinterpret_cast<const float4*>(&g_po[0][e0]);
    float4 b = *reinterpret_cast<const float4*>(&g_po[1][e0]);
    float4 v = make_float4(a.x + b.x, a.y + b.y, a.z + b.z, a.w + b.w);
    float* orow = Out + (size_t)row * (HD * 16) + col;
    #pragma unroll
    for (int h = 0; h < 16; h++)
        *reinterpret_cast<float4*>(orow + h * HD) = v;
}

// ====================================================================
extern "C" void kernel_launch(void* const* d_in, const int* in_sizes, int n_in,
                              void* d_out, int out_size)
{
    const float* x  = (const float*)d_in[0];
    const float* Wq = (const float*)d_in[1];
    const float* Wk = (const float*)d_in[2];
    const float* Wv = (const float*)d_in[3];
    float* out = (float*)d_out;

    cudaFuncSetAttribute(qkv_kernel,    cudaFuncAttributeMaxDynamicSharedMemorySize, QKV_SMEM);
    cudaFuncSetAttribute(scores_kernel, cudaFuncAttributeMaxDynamicSharedMemorySize, SCR_SMEM);
    cudaFuncSetAttribute(pv_kernel,     cudaFuncAttributeMaxDynamicSharedMemorySize, PV_SMEM);

    split_kernel<<<8192 + 96, 256>>>(x, Wq, Wk, Wv);
    qkv_kernel<<<NROWS/128, 256, QKV_SMEM>>>();
    scores_kernel<<<dim3(SEQ/128, SEQ/128, BATCH), 256, SCR_SMEM>>>();
    vscale_kernel<<<NROWS/256, 256>>>();
    pv_kernel<<<dim3(SEQ/128, 2, BATCH), 256, PV_SMEM>>>();
    outred_kernel<<<(NROWS*HD/4)/256, 256>>>(out);
}

// round 7
// speedup vs baseline: 2.8991x; 1.1005x over previous
#include <cuda_runtime.h>
#include <cuda_bf16.h>

#define BATCH 8
#define SEQ   2048
#define EMB   1024
#define HD    64
#define NROWS (BATCH*SEQ)   // 16384

typedef unsigned int u32;
typedef unsigned long long u64;

// ================= device scratch (allocation-free rule) =================
// W combined: [192 rows][32 k-chunks][64 cols: 0-31 hi, 32-63 lo]
__device__ __nv_bfloat16 g_wc[192*2048];
__device__ __nv_bfloat16 g_qh[NROWS*HD], g_ql[NROWS*HD];
__device__ __nv_bfloat16 g_kh[NROWS*HD], g_kl[NROWS*HD];
__device__ float         g_vf[NROWS*HD];
__device__ __nv_bfloat16 g_vth[BATCH*HD*SEQ], g_vtl[BATCH*HD*SEQ];  // [b][d][j]
__device__ __nv_bfloat16 g_eh[(size_t)BATCH*SEQ*SEQ];               // 64MB
__device__ __nv_bfloat16 g_el[(size_t)BATCH*SEQ*SEQ];               // 64MB
__device__ float         g_Dp[16][NROWS];                           // col-sum partials

// ================= helpers =================
__device__ __forceinline__ u32 smem_to_u32(const void* p) {
    u32 a;
    asm("{ .reg .u64 t; cvta.to.shared.u64 t, %1; cvt.u32.u64 %0, t; }" : "=r"(a) : "l"(p));
    return a;
}
__device__ __forceinline__ u32 swz(u32 off) { return off ^ ((off >> 3) & 0x70); }
__device__ __forceinline__ float bfhi(float x) {
    return __bfloat162float(__float2bfloat16_rn(x));
}
__device__ __forceinline__ u32 pkbf(float a, float b) {
    __nv_bfloat162 t = __floats2bfloat162_rn(a, b);
    return *reinterpret_cast<u32*>(&t);
}
__device__ __forceinline__ void ldmx4(u32* r, u32 addr) {
    asm volatile("ldmatrix.sync.aligned.m8n8.x4.shared.b16 {%0,%1,%2,%3}, [%4];"
        : "=r"(r[0]), "=r"(r[1]), "=r"(r[2]), "=r"(r[3]) : "r"(addr));
}
__device__ __forceinline__ void mma16816(float* d, const u32* a, const u32* b) {
    asm volatile("mma.sync.aligned.m16n8k16.row.col.f32.bf16.bf16.f32 "
        "{%0,%1,%2,%3}, {%4,%5,%6,%7}, {%8,%9}, {%0,%1,%2,%3};"
        : "+f"(d[0]), "+f"(d[1]), "+f"(d[2]), "+f"(d[3])
        : "r"(a[0]), "r"(a[1]), "r"(a[2]), "r"(a[3]), "r"(b[0]), "r"(b[1]));
}
__device__ __forceinline__ u32 a_addr(u32 base, int row0, int k0, int lane) {
    int row = row0 + (lane & 15);
    int kb  = k0 + ((lane >> 4) << 3);
    return base + swz((u32)(row * 128 + kb * 2));
}
__device__ __forceinline__ u32 b_addr(u32 base, int n0, int k0, int lane) {
    int n  = n0 + (lane & 7) + ((lane & 16) >> 1);
    int kb = k0 + (lane & 8);
    return base + swz((u32)(n * 128 + kb * 2));
}
__device__ __forceinline__ void cpa16(u32 dst, const void* src) {
    asm volatile("cp.async.cg.shared.global [%0], [%1], 16;" :: "r"(dst), "l"(src) : "memory");
}
#define CP_COMMIT() asm volatile("cp.async.commit_group;" ::: "memory")
#define CP_WAIT(n)  asm volatile("cp.async.wait_group %0;" :: "n"(n) : "memory")

// ====================================================================
// K0: split stacked W into combined hi|lo layout g_wc. grid=192, 256 thr.
// ====================================================================
__global__ void __launch_bounds__(256) splitw_kernel(
    const float* __restrict__ Wq, const float* __restrict__ Wk,
    const float* __restrict__ Wv)
{
    const int r = blockIdx.x;
    const int k = threadIdx.x * 4;
    const float* wr = (r < 64)  ? Wq + (size_t)r * EMB
                    : (r < 128) ? Wk + (size_t)(r - 64) * EMB
                                : Wv + (size_t)(r - 128) * EMB;
    float4 v = *reinterpret_cast<const float4*>(wr + k);
    float h0 = bfhi(v.x), h1 = bfhi(v.y), h2 = bfhi(v.z), h3 = bfhi(v.w);
    __nv_bfloat16* dst = g_wc + (size_t)r * 2048 + (k >> 5) * 64 + (k & 31);
    *reinterpret_cast<uint2*>(dst)      = make_uint2(pkbf(h0, h1), pkbf(h2, h3));
    *reinterpret_cast<uint2*>(dst + 32) = make_uint2(pkbf(v.x - h0, v.y - h1), pkbf(v.z - h2, v.w - h3));
}

// ====================================================================
// K1: fused QKV GEMM.  [16384,192] = X @ Wstack^T, 3-term bf16 split.
// BM=64, k-chunk=32, grid=256 CTAs, 256 thr (warps 2m x 4n, 32x48),
// occ 2. X loaded fp32 via cp.async, converted in-kernel.
// ====================================================================
#define QKV_STAGE 32768
#define QKV_XC    65536
#define QKV_SMEM  (QKV_XC + 2*8192)    // 81920

__global__ void __launch_bounds__(256, 2) qkv_kernel(const float* __restrict__ X)
{
    extern __shared__ char smem[];
    const u32 sb = smem_to_u32(smem);
    const int tid = threadIdx.x, lane = tid & 31, w = tid >> 5;
    const int wm = w & 1, wn = w >> 1;
    const int m0 = blockIdx.x * 64;

    auto issue = [&](int c) {
        const u32 base = sb + (c & 1) * QKV_STAGE;
        #pragma unroll
        for (int it = 0; it < 2; it++) {       // Xf: 64 rows x 32 f32 (128B/row)
            int idx = tid + it * 256, r = idx >> 3, u = idx & 7;
            cpa16(base + (u32)(r * 128 + u * 16),
                  X + (size_t)(m0 + r) * EMB + c * 32 + u * 4);
        }
        #pragma unroll
        for (int it = 0; it < 6; it++) {       // Wc: 192 rows x 64 bf16 (128B/row)
            int idx = tid + it * 256, r = idx >> 3, u = idx & 7;
            cpa16(base + 8192 + swz((u32)(r * 128 + u * 16)),
                  g_wc + (size_t)r * 2048 + c * 64 + u * 8);
        }
    };

    float acc[2][6][4];
    #pragma unroll
    for (int a = 0; a < 2; a++)
        #pragma unroll
        for (int n = 0; n < 6; n++)
            #pragma unroll
            for (int i = 0; i < 4; i++) acc[a][n][i] = 0.0f;

    issue(0); CP_COMMIT();
    const int NC = EMB / 32;   // 32
    for (int c = 0; c < NC; c++) {
        CP_WAIT(0);
        __syncthreads();                       // stage c ready; prev MMA done
        if (c + 1 < NC) { issue(c + 1); CP_COMMIT(); }

        // convert Xf(c) -> Xc[c&1] (hi k 0-31, lo k 32-63 i.e. bytes 64-127)
        const char* xfp = smem + (c & 1) * QKV_STAGE;
        char* xcp = smem + QKV_XC + (c & 1) * 8192;
        #pragma unroll
        for (int it = 0; it < 2; it++) {
            int idx = tid + it * 256, r = idx >> 3, q = idx & 7;
            float4 v = *reinterpret_cast<const float4*>(xfp + r * 128 + q * 16);
            float h0 = bfhi(v.x), h1 = bfhi(v.y), h2 = bfhi(v.z), h3 = bfhi(v.w);
            *reinterpret_cast<uint2*>(xcp + swz((u32)(r * 128 + q * 8))) =
                make_uint2(pkbf(h0, h1), pkbf(h2, h3));
            *reinterpret_cast<uint2*>(xcp + swz((u32)(r * 128 + 64 + q * 8))) =
                make_uint2(pkbf(v.x - h0, v.y - h1), pkbf(v.z - h2, v.w - h3));
        }
        __syncthreads();                       // Xc ready

        const u32 xc = sb + QKV_XC + (c & 1) * 8192;
        const u32 wc = sb + (c & 1) * QKV_STAGE + 8192;
        #pragma unroll
        for (int ks = 0; ks < 2; ks++) {
            const int kk = ks * 16;
            u32 ah[2][4], al[2][4];
            ldmx4(ah[0], a_addr(xc, wm * 32,      kk,      lane));
            ldmx4(ah[1], a_addr(xc, wm * 32 + 16, kk,      lane));
            ldmx4(al[0], a_addr(xc, wm * 32,      kk + 32, lane));
            ldmx4(al[1], a_addr(xc, wm * 32 + 16, kk + 32, lane));
            #pragma unroll
            for (int np = 0; np < 3; np++) {
                u32 bh[4], bl[4];
                ldmx4(bh, b_addr(wc, wn * 48 + np * 16, kk,      lane));
                ldmx4(bl, b_addr(wc, wn * 48 + np * 16, kk + 32, lane));
                #pragma unroll
                for (int mt = 0; mt < 2; mt++) {
                    mma16816(acc[mt][2*np],   ah[mt], bh);
                    mma16816(acc[mt][2*np],   ah[mt], bl);
                    mma16816(acc[mt][2*np],   al[mt], bh);
                    mma16816(acc[mt][2*np+1], ah[mt], bh + 2);
                    mma16816(acc[mt][2*np+1], ah[mt], bl + 2);
                    mma16816(acc[mt][2*np+1], al[mt], bh + 2);
                }
            }
        }
    }

    // epilogue: cols <64 -> Q (split), <128 -> K (split), else V (fp32)
    #pragma unroll
    for (int mt = 0; mt < 2; mt++) {
        #pragma unroll
        for (int nt = 0; nt < 6; nt++) {
            const int col = wn * 48 + nt * 8 + 2 * (lane & 3);
            const int r0  = m0 + wm * 32 + mt * 16 + (lane >> 2);
            const float* f = acc[mt][nt];
            #pragma unroll
            for (int half = 0; half < 2; half++) {
                const int row = r0 + 8 * half;
                const float x0 = f[2*half], x1 = f[2*half + 1];
                if (col < 64) {
                    float h0 = bfhi(x0), h1 = bfhi(x1);
                    *reinterpret_cast<u32*>(g_qh + (size_t)row * HD + col) = pkbf(h0, h1);
                    *reinterpret_cast<u32*>(g_ql + (size_t)row * HD + col) = pkbf(x0 - h0, x1 - h1);
                } else if (col < 128) {
                    float h0 = bfhi(x0), h1 = bfhi(x1);
                    *reinterpret_cast<u32*>(g_kh + (size_t)row * HD + col - 64) = pkbf(h0, h1);
                    *reinterpret_cast<u32*>(g_kl + (size_t)row * HD + col - 64) = pkbf(x0 - h0, x1 - h1);
                } else {
                    *reinterpret_cast<float2*>(g_vf + (size_t)row * HD + col - 128) = make_float2(x0, x1);
                }
            }
        }
    }
}

// ====================================================================
// K2: scores tile [128 x 128] = Q @ K^T (3-term), epilogue: exp, col-sum
// partials (softmax over QUERY axis), bf16 split, staged coalesced store.
// grid = (16 j, 16 i, 8 b), 256 thr, warps 4m x 2n (warp 32x64).
// ====================================================================
#define SCR_SMEM (65536 + 2048)

__global__ void __launch_bounds__(256, 2) scores_kernel()
{
    extern __shared__ char smem[];
    const u32 sb = smem_to_u32(smem);
    const int tid = threadIdx.x, lane = tid & 31, w = tid >> 5;
    const int wm = w & 3, wn = w >> 2;
    const int b = blockIdx.z, i0 = blockIdx.y * 128, j0 = blockIdx.x * 128;

    {
        const __nv_bfloat16* srcs[4] = {
            g_qh + ((size_t)b * SEQ + i0) * HD, g_ql + ((size_t)b * SEQ + i0) * HD,
            g_kh + ((size_t)b * SEQ + j0) * HD, g_kl + ((size_t)b * SEQ + j0) * HD };
        #pragma unroll
        for (int s = 0; s < 4; s++) {
            #pragma unroll
            for (int it = 0; it < 4; it++) {
                int idx = tid + it * 256, r = idx >> 3, u = idx & 7;
                cpa16(sb + s * 16384 + swz((u32)(r * 128 + u * 16)),
                      srcs[s] + (size_t)r * HD + u * 8);
            }
        }
        CP_COMMIT(); CP_WAIT(0);
    }
    __syncthreads();

    float acc[2][8][4];
    #pragma unroll
    for (int a = 0; a < 2; a++)
        #pragma unroll
        for (int n = 0; n < 8; n++)
            #pragma unroll
            for (int i = 0; i < 4; i++) acc[a][n][i] = 0.0f;

    const u32 qh = sb, ql = sb + 16384, kh = sb + 32768, kl = sb + 49152;
    #pragma unroll
    for (int ks = 0; ks < 4; ks++) {
        const int kk = ks * 16;
        u32 ah[2][4], al[2][4];
        ldmx4(ah[0], a_addr(qh, wm * 32,      kk, lane));
        ldmx4(ah[1], a_addr(qh, wm * 32 + 16, kk, lane));
        ldmx4(al[0], a_addr(ql, wm * 32,      kk, lane));
        ldmx4(al[1], a_addr(ql, wm * 32 + 16, kk, lane));
        #pragma unroll
        for (int np = 0; np < 4; np++) {
            u32 bh[4], bl[4];
            ldmx4(bh, b_addr(kh, wn * 64 + np * 16, kk, lane));
            ldmx4(bl, b_addr(kl, wn * 64 + np * 16, kk, lane));
            #pragma unroll
            for (int mt = 0; mt < 2; mt++) {
                mma16816(acc[mt][2*np],   ah[mt], bh);
                mma16816(acc[mt][2*np],   ah[mt], bl);
                mma16816(acc[mt][2*np],   al[mt], bh);
                mma16816(acc[mt][2*np+1], ah[mt], bh + 2);
                mma16816(acc[mt][2*np+1], ah[mt], bl + 2);
                mma16816(acc[mt][2*np+1], al[mt], bh + 2);
            }
        }
    }

    #pragma unroll
    for (int mt = 0; mt < 2; mt++)
        #pragma unroll
        for (int nt = 0; nt < 8; nt++)
            #pragma unroll
            for (int i = 0; i < 4; i++)
                acc[mt][nt][i] = __expf(acc[mt][nt][i]);

    // deterministic column-sum partials
    float* csm = reinterpret_cast<float*>(smem + 65536);   // [4][128]
    {
        float cs[8][2];
        #pragma unroll
        for (int nt = 0; nt < 8; nt++) {
            #pragma unroll
            for (int cc = 0; cc < 2; cc++) {
                float v = acc[0][nt][cc] + acc[0][nt][cc+2] + acc[1][nt][cc] + acc[1][nt][cc+2];
                v += __shfl_xor_sync(0xffffffffu, v, 4);
                v += __shfl_xor_sync(0xffffffffu, v, 8);
                v += __shfl_xor_sync(0xffffffffu, v, 16);
                cs[nt][cc] = v;
            }
        }
        if (lane < 4) {
            #pragma unroll
            for (int nt = 0; nt < 8; nt++)
                *reinterpret_cast<float2*>(&csm[wm * 128 + wn * 64 + nt * 8 + 2 * lane]) =
                    make_float2(cs[nt][0], cs[nt][1]);
        }
    }
    __syncthreads();

    #pragma unroll
    for (int mt = 0; mt < 2; mt++) {
        #pragma unroll
        for (int nt = 0; nt < 8; nt++) {
            const int colp = wn * 64 + nt * 8 + 2 * (lane & 3);
            #pragma unroll
            for (int half = 0; half < 2; half++) {
                const int row = wm * 32 + mt * 16 + (lane >> 2) + 8 * half;
                const float x0 = acc[mt][nt][2*half], x1 = acc[mt][nt][2*half + 1];
                const float h0 = bfhi(x0), h1 = bfhi(x1);
                const u32 off = swz((u32)(row * 256 + colp * 2));
                *reinterpret_cast<u32*>(smem + off)         = pkbf(h0, h1);
                *reinterpret_cast<u32*>(smem + 32768 + off) = pkbf(x0 - h0, x1 - h1);
            }
        }
    }
    if (tid < 128) {
        float s = csm[tid] + csm[128 + tid] + csm[256 + tid] + csm[384 + tid];
        g_Dp[blockIdx.y][b * SEQ + j0 + tid] = s;
    }
    __syncthreads();

    const size_t ebase = ((size_t)b * SEQ + i0) * SEQ + j0;
    #pragma unroll
    for (int it = 0; it < 8; it++) {
        int u = tid + it * 256, r = u >> 4, cu = u & 15;
        uint4 vh = *reinterpret_cast<const uint4*>(smem + swz((u32)(u * 16)));
        uint4 vl = *reinterpret_cast<const uint4*>(smem + 32768 + swz((u32)(u * 16)));
        *reinterpret_cast<uint4*>(g_eh + ebase + (size_t)r * SEQ + cu * 8) = vh;
        *reinterpret_cast<uint4*>(g_el + ebase + (size_t)r * SEQ + cu * 8) = vl;
    }
}

// ====================================================================
// K3: V' = V / D, transpose to [b][d][j], split bf16. Tiled + coalesced.
// grid (32 j-tiles, 8 b), 256 thr.
// ====================================================================
__global__ void __launch_bounds__(256) vscale_kernel()
{
    __shared__ float dinv[64];
    __shared__ __nv_bfloat16 th[64][80], tl[64][80];
    const int tid = threadIdx.x;
    const int b = blockIdx.y, j0 = blockIdx.x * 64;

    if (tid < 64) {
        const int t = b * SEQ + j0 + tid;
        float D = 0.0f;
        #pragma unroll
        for (int p = 0; p < 16; p++) D += g_Dp[p][t];
        dinv[tid] = 1.0f / D;
    }
    __syncthreads();

    #pragma unroll
    for (int it = 0; it < 4; it++) {
        int idx = tid + it * 256, r = idx >> 4, q = idx & 15;   // r = local j
        float4 v = *reinterpret_cast<const float4*>(
            g_vf + ((size_t)b * SEQ + j0 + r) * HD + q * 4);
        const float s = dinv[r];
        float xs[4] = {v.x * s, v.y * s, v.z * s, v.w * s};
        #pragma unroll
        for (int i = 0; i < 4; i++) {
            float h = bfhi(xs[i]);
            th[q * 4 + i][r] = __float2bfloat16_rn(xs[i]);
            tl[q * 4 + i][r] = __float2bfloat16_rn(xs[i] - h);
        }
    }
    __syncthreads();

    #pragma unroll
    for (int it = 0; it < 2; it++) {
        int idx = tid + it * 256, d = idx >> 3, u = idx & 7;
        size_t dst = ((size_t)b * HD + d) * SEQ + j0 + u * 8;
        *reinterpret_cast<uint4*>(g_vth + dst) = *reinterpret_cast<const uint4*>(&th[d][u * 8]);
        *reinterpret_cast<uint4*>(g_vtl + dst) = *reinterpret_cast<const uint4*>(&tl[d][u * 8]);
    }
}

// ====================================================================
// K4: O[b] = E[b] @ V' (3-term), BM=64, direct x16-tiled output.
// grid (32 i, 8 b) = 256 CTAs, 256 thr (warps 2m x 4n, 32x16), occ 2.
// ====================================================================
#define PV_STAGE 32768
#define PV_SMEM  (2*PV_STAGE)    // 64 KB

__global__ void __launch_bounds__(256, 2) pv_kernel(float* __restrict__ Out)
{
    extern __shared__ char smem[];
    const u32 sb = smem_to_u32(smem);
    const int tid = threadIdx.x, lane = tid & 31, w = tid >> 5;
    const int wm = w & 1, wn = w >> 1;
    const int b = blockIdx.y, i0 = blockIdx.x * 64;

    auto issue = [&](int c) {
        const u32 base = sb + (c & 1) * PV_STAGE;
        const int k0 = c * 64;
        #pragma unroll
        for (int it = 0; it < 2; it++) {       // Eh/El: 64 rows x 128B
            int idx = tid + it * 256, r = idx >> 3, u = idx & 7;
            size_t so = ((size_t)b * SEQ + i0 + r) * SEQ + k0 + u * 8;
            u32 d = base + swz((u32)(r * 128 + u * 16));
            cpa16(d,        g_eh + so);
            cpa16(d + 8192, g_el + so);
        }
        #pragma unroll
        for (int it = 0; it < 2; it++) {       // Vh/Vl: 64 d-rows x 128B
            int idx = tid + it * 256, r = idx >> 3, u = idx & 7;
            size_t so = ((size_t)b * HD + r) * SEQ + k0 + u * 8;
            u32 d = base + 16384 + swz((u32)(r * 128 + u * 16));
            cpa16(d,        g_vth + so);
            cpa16(d + 8192, g_vtl + so);
        }
    };

    float acc[2][2][4];
    #pragma unroll
    for (int a = 0; a < 2; a++)
        #pragma unroll
        for (int n = 0; n < 2; n++)
            #pragma unroll
            for (int i = 0; i < 4; i++) acc[a][n][i] = 0.0f;

    issue(0); CP_COMMIT();
    const int NC = SEQ / 64;   // 32
    for (int c = 0; c < NC; c++) {
        if (c + 1 < NC) { issue(c + 1); CP_COMMIT(); CP_WAIT(1); }
        else            { CP_WAIT(0); }
        __syncthreads();
        const u32 eh = sb + (c & 1) * PV_STAGE, el = eh + 8192;
        const u32 vh = eh + 16384, vl = eh + 24576;
        #pragma unroll
        for (int ks = 0; ks < 4; ks++) {
            const int kk = ks * 16;
            u32 ah[2][4], al[2][4];
            ldmx4(ah[0], a_addr(eh, wm * 32,      kk, lane));
            ldmx4(ah[1], a_addr(eh, wm * 32 + 16, kk, lane));
            ldmx4(al[0], a_addr(el, wm * 32,      kk, lane));
            ldmx4(al[1], a_addr(el, wm * 32 + 16, kk, lane));
            u32 bh[4], bl[4];
            ldmx4(bh, b_addr(vh, wn * 16, kk, lane));
            ldmx4(bl, b_addr(vl, wn * 16, kk, lane));
            #pragma unroll
            for (int mt = 0; mt < 2; mt++) {
                mma16816(acc[mt][0], ah[mt], bh);
                mma16816(acc[mt][0], ah[mt], bl);
                mma16816(acc[mt][0], al[mt], bh);
                mma16816(acc[mt][1], ah[mt], bh + 2);
                mma16816(acc[mt][1], ah[mt], bl + 2);
                mma16816(acc[mt][1], al[mt], bh + 2);
            }
        }
        __syncthreads();
    }

    // write final output, tiled x16 across heads
    #pragma unroll
    for (int mt = 0; mt < 2; mt++) {
        #pragma unroll
        for (int nt = 0; nt < 2; nt++) {
            const int col = wn * 16 + nt * 8 + 2 * (lane & 3);
            #pragma unroll
            for (int half = 0; half < 2; half++) {
                const int row = i0 + wm * 32 + mt * 16 + (lane >> 2) + 8 * half;
                float2 v = make_float2(acc[mt][nt][2*half], acc[mt][nt][2*half + 1]);
                float* orow = Out + ((size_t)b * SEQ + row) * (size_t)(HD * 16) + col;
                #pragma unroll
                for (int h = 0; h < 16; h++)
                    *reinterpret_cast<float2*>(orow + h * HD) = v;
            }
        }
    }
}

// ====================================================================
extern "C" void kernel_launch(void* const* d_in, const int* in_sizes, int n_in,
                              void* d_out, int out_size)
{
    const float* x  = (const float*)d_in[0];
    const float* Wq = (const float*)d_in[1];
    const float* Wk = (const float*)d_in[2];
    const float* Wv = (const float*)d_in[3];
    float* out = (float*)d_out;

    cudaFuncSetAttribute(qkv_kernel,    cudaFuncAttributeMaxDynamicSharedMemorySize, QKV_SMEM);
    cudaFuncSetAttribute(scores_kernel, cudaFuncAttributeMaxDynamicSharedMemorySize, SCR_SMEM);
    cudaFuncSetAttribute(pv_kernel,     cudaFuncAttributeMaxDynamicSharedMemorySize, PV_SMEM);

    splitw_kernel<<<192, 256>>>(Wq, Wk, Wv);
    qkv_kernel<<<NROWS/64, 256, QKV_SMEM>>>(x);
    scores_kernel<<<dim3(SEQ/128, SEQ/128, BATCH), 256, SCR_SMEM>>>();
    vscale_kernel<<<dim3(SEQ/64, BATCH), 256>>>();
    pv_kernel<<<dim3(SEQ/64, BATCH), 256, PV_SMEM>>>(out);
}